// round 15
// baseline (speedup 1.0000x reference)
#include <cuda_runtime.h>
#include <cuda_fp16.h>
#include <cstdint>
#include <math.h>

#define BB 2
#define SS 4096
#define DD 768
#define HH 12
#define LL 2
#define DHH 64
#define WW 256
#define GG 64
#define FFN 3072
#define SEPID 2
#define NEGV -1000000000.0f
#define BS (BB*SS)
#define QS (5*DD)
#define NSEG 8
#define SEGS (SS/NSEG)
#define BH (BB*HH)

#define WSZ_DD (DD*DD)
#define OFF_Q  0
#define OFF_K  (1*WSZ_DD)
#define OFF_V  (2*WSZ_DD)
#define OFF_KG (3*WSZ_DD)
#define OFF_VG (4*WSZ_DD)
#define OFF_QG (5*WSZ_DD)
#define OFF_O  (6*WSZ_DD)
#define OFF_F1 (7*WSZ_DD)
#define OFF_F2 (7*WSZ_DD + DD*FFN)
#define LWOFF  (7*WSZ_DD + 2*DD*FFN)

// ---------------- scratch ----------------
__device__ float g_x[BS*DD];
__device__ float g_qkv[(size_t)BS*QS];
__device__ float g_tmp[BS*DD];
__device__ float g_qg[BB*GG*DD];
__device__ float g_bcat[2*QS];
__device__ float g_pacc[NSEG*BH*GG*64];
__device__ float g_pml[NSEG*BH*GG*2];
__device__ int   g_idxg[BB*GG];
__device__ unsigned char g_klo[BS];

__device__ __align__(16) __half g_w[2*LWOFF];
__device__ __align__(16) __half g_ahi[BS*FFN];
__device__ __align__(16) __half g_alo[BS*FFN];
__device__ __align__(16) __half g_xhi[BS*DD];
__device__ __align__(16) __half g_xlo[BS*DD];
__device__ __align__(16) __half g_xghi[BB*GG*DD];
__device__ __align__(16) __half g_xglo[BB*GG*DD];
__device__ __align__(16) __half g_bqh[BS*DD];
__device__ __align__(16) __half g_bql[BS*DD];
__device__ __align__(16) __half g_bkh[BS*DD];
__device__ __align__(16) __half g_bvh[BS*DD];
__device__ __align__(16) __half g_bvl[BS*DD];

// ---------------- helpers ----------------
__device__ __forceinline__ uint32_t smem_u32(const void* p) {
    uint32_t a;
    asm("{ .reg .u64 t; cvta.to.shared.u64 t, %1; cvt.u32.u64 %0, t; }" : "=r"(a) : "l"(p));
    return a;
}

__device__ __forceinline__ void cp16(uint32_t dst, const void* src) {
    asm volatile("cp.async.ca.shared.global [%0], [%1], 16;" :: "r"(dst), "l"(src));
}
// zero-fill variant: src-size 0 pads the full 16B with zeros
__device__ __forceinline__ void cp16z(uint32_t dst, const void* src, bool valid) {
    int sz = valid ? 16 : 0;
    asm volatile("cp.async.ca.shared.global [%0], [%1], 16, %2;"
                 :: "r"(dst), "l"(src), "r"(sz));
}
#define CP_COMMIT() asm volatile("cp.async.commit_group;" ::: "memory")
#define CP_WAIT2()  asm volatile("cp.async.wait_group 2;" ::: "memory")
#define CP_WAIT1()  asm volatile("cp.async.wait_group 1;" ::: "memory")

__device__ __forceinline__ void ldmat4(uint32_t& r0, uint32_t& r1, uint32_t& r2, uint32_t& r3,
                                       uint32_t addr) {
    asm volatile("ldmatrix.sync.aligned.m8n8.x4.shared.b16 {%0,%1,%2,%3}, [%4];"
        : "=r"(r0), "=r"(r1), "=r"(r2), "=r"(r3) : "r"(addr));
}

__device__ __forceinline__ void ldmat4t(uint32_t& r0, uint32_t& r1, uint32_t& r2, uint32_t& r3,
                                        uint32_t addr) {
    asm volatile("ldmatrix.sync.aligned.m8n8.x4.trans.shared.b16 {%0,%1,%2,%3}, [%4];"
        : "=r"(r0), "=r"(r1), "=r"(r2), "=r"(r3) : "r"(addr));
}

__device__ __forceinline__ void mma16816(float* d, const uint32_t* a, const uint32_t* b) {
    asm volatile("mma.sync.aligned.m16n8k16.row.col.f32.f16.f16.f32 "
        "{%0,%1,%2,%3}, {%4,%5,%6,%7}, {%8,%9}, {%0,%1,%2,%3};"
        : "+f"(d[0]), "+f"(d[1]), "+f"(d[2]), "+f"(d[3])
        : "r"(a[0]), "r"(a[1]), "r"(a[2]), "r"(a[3]), "r"(b[0]), "r"(b[1]));
}

__device__ __forceinline__ uint32_t packh2(float a, float b) {
    __half2 h = __floats2half2_rn(a, b);
    return *(uint32_t*)&h;
}

__device__ __forceinline__ float gelu_f(float v) {
    return 0.5f*v*(1.f + tanhf(0.7978845608028654f*(v + 0.044715f*v*v*v)));
}

// ---------------- block reductions ----------------
__device__ __forceinline__ float blk_sum(float v) {
    __shared__ float sm[33];
    int lane = threadIdx.x & 31, wid = threadIdx.x >> 5;
    #pragma unroll
    for (int o = 16; o; o >>= 1) v += __shfl_xor_sync(0xffffffffu, v, o);
    if (lane == 0) sm[wid] = v;
    __syncthreads();
    if (wid == 0) {
        int nw = (blockDim.x + 31) >> 5;
        float r = (lane < nw) ? sm[lane] : 0.f;
        #pragma unroll
        for (int o = 16; o; o >>= 1) r += __shfl_xor_sync(0xffffffffu, r, o);
        if (lane == 0) sm[32] = r;
    }
    __syncthreads();
    float r = sm[32];
    __syncthreads();
    return r;
}

// ---------------- prep ----------------
__global__ void prep_k(const int* __restrict__ ids, const int* __restrict__ am,
                       int* __restrict__ idxg, unsigned char* __restrict__ klo) {
    int b = blockIdx.x;
    for (int s = threadIdx.x; s < SS; s += blockDim.x) {
        bool g = (ids[b*SS+s] == SEPID) || (s == 0);
        klo[b*SS+s] = (am[b*SS+s] != 0 && !g) ? 1 : 0;
    }
    if (threadIdx.x == 0) {
        int cnt = 0;
        for (int s = 0; s < SS && cnt < GG; s++)
            if (ids[b*SS+s] == SEPID || s == 0) idxg[b*GG + cnt++] = s;
        for (; cnt < GG; cnt++) idxg[b*GG + cnt] = 0;
    }
}

// ---------------- embedding + LN ----------------
__global__ void embed_ln_k(const int* __restrict__ ids, const float* __restrict__ etok,
                           const float* __restrict__ epos, const float* __restrict__ lns,
                           const float* __restrict__ lnb, float* __restrict__ x,
                           __half* __restrict__ xhi, __half* __restrict__ xlo) {
    int row = blockIdx.x;
    int spos = row & (SS - 1);
    int id = ids[row];
    const float* te = etok + (size_t)id * DD;
    const float* pe = epos + (size_t)spos * DD;
    float v[3]; float sum = 0.f;
    #pragma unroll
    for (int i = 0; i < 3; i++) {
        int d = threadIdx.x + i*256;
        float val = te[d] + pe[d];
        v[i] = val; sum += val;
    }
    float mean = blk_sum(sum) * (1.0f/DD);
    float sq = 0.f;
    #pragma unroll
    for (int i = 0; i < 3; i++) { float c = v[i] - mean; sq += c*c; }
    float inv = rsqrtf(blk_sum(sq) * (1.0f/DD) + 1e-5f);
    #pragma unroll
    for (int i = 0; i < 3; i++) {
        int d = threadIdx.x + i*256;
        float o = (v[i] - mean)*inv*lns[d] + lnb[d];
        x[(size_t)row*DD + d] = o;
        __half h = __float2half(o);
        xhi[(size_t)row*DD + d] = h;
        xlo[(size_t)row*DD + d] = __float2half(o - __half2float(h));
    }
}

// ---------------- residual add + LN ----------------
__global__ void add_ln_k(float* __restrict__ x, const float* __restrict__ t,
                         const float* __restrict__ lns, const float* __restrict__ lnb,
                         __half* __restrict__ xhi, __half* __restrict__ xlo) {
    int row = blockIdx.x;
    size_t base = (size_t)row * DD;
    float v[3]; float sum = 0.f;
    #pragma unroll
    for (int i = 0; i < 3; i++) {
        int d = threadIdx.x + i*256;
        float val = x[base+d] + t[base+d];
        v[i] = val; sum += val;
    }
    float mean = blk_sum(sum) * (1.0f/DD);
    float sq = 0.f;
    #pragma unroll
    for (int i = 0; i < 3; i++) { float c = v[i] - mean; sq += c*c; }
    float inv = rsqrtf(blk_sum(sq) * (1.0f/DD) + 1e-5f);
    #pragma unroll
    for (int i = 0; i < 3; i++) {
        int d = threadIdx.x + i*256;
        float o = (v[i] - mean)*inv*lns[d] + lnb[d];
        x[base+d] = o;
        __half h = __float2half(o);
        xhi[base+d] = h;
        xlo[base+d] = __float2half(o - __half2float(h));
    }
}

// ---------------- conversions ----------------
__global__ void wsplit_t_k(const float* __restrict__ W, __half* __restrict__ hi,
                           int K, int N) {
    __shared__ float t[32][33];
    int n0 = blockIdx.x*32, k0 = blockIdx.y*32;
    int tx = threadIdx.x, ty = threadIdx.y;
    #pragma unroll
    for (int i = 0; i < 4; i++)
        t[ty+8*i][tx] = W[(size_t)(k0+ty+8*i)*N + n0 + tx];
    __syncthreads();
    #pragma unroll
    for (int i = 0; i < 4; i++) {
        float v = t[tx][ty+8*i];
        hi[(size_t)(n0+ty+8*i)*K + k0 + tx] = __float2half(v);
    }
}

__global__ void bcat_k(const float* __restrict__ b0, const float* __restrict__ b1,
                       const float* __restrict__ b2, const float* __restrict__ b3,
                       const float* __restrict__ b4, float* __restrict__ dst) {
    int i = blockIdx.x*256 + threadIdx.x;
    if (i >= QS) return;
    int seg = i / DD, off = i - seg*DD;
    const float* src = (seg == 0) ? b0 : (seg == 1) ? b1 : (seg == 2) ? b2 : (seg == 3) ? b3 : b4;
    dst[i] = src[off];
}

// ---------------- tensor-core GEMM: BK=32, cp.async 4-stage, fp16 2-pass --------
#define SPAD 40
#define STG_BYTES (128*SPAD*2)
#define SMEM_GEMM (8*STG_BYTES)

template<int MODE>
__global__ void __launch_bounds__(256, 2) tgemm_k(
        const __half* __restrict__ Ahi_, const __half* __restrict__ Alo_,
        const __half* __restrict__ B_,
        const float* __restrict__ bias_, float* __restrict__ C,
        __half* __restrict__ Chi, __half* __restrict__ Clo,
        int M, int N_, int K,
        const __half* A2hi, const __half* A2lo, const __half* B2,
        const float* bias2, float* C2) {
    extern __shared__ char smem[];
    const uint32_t sm0 = smem_u32(smem);
    const bool qgp = (MODE == 2) && ((int)blockIdx.y == (BS >> 7));
    if (qgp && blockIdx.x >= DD/128) return;
    const __half* Ahi = qgp ? A2hi : Ahi_;
    const __half* Alo = qgp ? A2lo : Alo_;
    const __half* B   = qgp ? B2   : B_;
    const float* bias = qgp ? bias2 : bias_;
    const int N = qgp ? DD : N_;
    const int bn = blockIdx.x << 7;
    const int bm = qgp ? 0 : (blockIdx.y << 7);
    const int tid = threadIdx.x, wid = tid >> 5, lane = tid & 31;
    const int wm = (wid >> 2) << 6;
    const int wn = (wid & 3) << 5;

    float acc[4][4][4];
    #pragma unroll
    for (int i = 0; i < 4; i++)
        #pragma unroll
        for (int j = 0; j < 4; j++)
            #pragma unroll
            for (int r = 0; r < 4; r++) acc[i][j][r] = 0.f;

    const int KC = K >> 5;
    const int total = 2 * KC;
    const __half* Aps[2] = {Ahi, Alo};

    const int r0 = tid >> 2, c0 = (tid & 3) << 3;
    const int r1 = r0 + 64;
    const uint32_t dA0 = (uint32_t)((r0*SPAD + c0) << 1);
    const uint32_t dA1 = (uint32_t)((r1*SPAD + c0) << 1);

    const int lrow = lane & 15, lcol = (lane >> 4) << 3;
    const uint32_t offA = (uint32_t)(((wm + lrow) * SPAD + lcol) << 1);
    const uint32_t offB = (uint32_t)(((wn + lrow) * SPAD + lcol) << 1) + 4*STG_BYTES;

    #pragma unroll
    for (int p = 0; p < 3; p++) {
        const int pass = (p < KC) ? 0 : 1;
        const int kc = p - pass*KC;
        const __half* Ap = Aps[pass];
        const int kb = kc << 5;
        const uint32_t sa = sm0 + p*STG_BYTES;
        const uint32_t sb = sm0 + 4*STG_BYTES + p*STG_BYTES;
        cp16(sa + dA0, Ap + (size_t)(bm + r0)*K + kb + c0);
        cp16(sa + dA1, Ap + (size_t)(bm + r1)*K + kb + c0);
        cp16(sb + dA0, B + (size_t)(bn + r0)*K + kb + c0);
        cp16(sb + dA1, B + (size_t)(bn + r1)*K + kb + c0);
        CP_COMMIT();
    }

    for (int s = 0; s < total; s++) {
        CP_WAIT2();
        __syncthreads();
        const int p = s + 3;
        if (p < total) {
            const int pass = (p < KC) ? 0 : 1;
            const int kc = p - pass*KC;
            const __half* Ap = Aps[pass];
            const int kb = kc << 5;
            const int st2 = p & 3;
            const uint32_t sa = sm0 + st2*STG_BYTES;
            const uint32_t sb = sm0 + 4*STG_BYTES + st2*STG_BYTES;
            cp16(sa + dA0, Ap + (size_t)(bm + r0)*K + kb + c0);
            cp16(sa + dA1, Ap + (size_t)(bm + r1)*K + kb + c0);
            cp16(sb + dA0, B + (size_t)(bn + r0)*K + kb + c0);
            cp16(sb + dA1, B + (size_t)(bn + r1)*K + kb + c0);
        }
        CP_COMMIT();
        const int stg = s & 3;
        const uint32_t abase = sm0 + stg*STG_BYTES + offA;
        const uint32_t bbase = sm0 + stg*STG_BYTES + offB;
        #pragma unroll
        for (int ks = 0; ks < 2; ks++) {
            uint32_t af[4][4], bf[4][2];
            #pragma unroll
            for (int mt = 0; mt < 4; mt++)
                ldmat4(af[mt][0], af[mt][1], af[mt][2], af[mt][3],
                       abase + (uint32_t)(((mt << 4) * SPAD + (ks << 4)) << 1));
            #pragma unroll
            for (int np = 0; np < 2; np++) {
                uint32_t m0, m1, m2, m3;
                ldmat4(m0, m1, m2, m3,
                       bbase + (uint32_t)(((np << 4) * SPAD + (ks << 4)) << 1));
                bf[2*np][0] = m0; bf[2*np+1][0] = m1;
                bf[2*np][1] = m2; bf[2*np+1][1] = m3;
            }
            #pragma unroll
            for (int mt = 0; mt < 4; mt++)
                #pragma unroll
                for (int nt = 0; nt < 4; nt++)
                    mma16816(acc[mt][nt], af[mt], bf[nt]);
        }
    }

    const int mrow = lane >> 2, ncol = (lane & 3) << 1;
    const int seg = bn / DD;
    #pragma unroll
    for (int mt = 0; mt < 4; mt++) {
        #pragma unroll
        for (int nt = 0; nt < 4; nt++) {
            int r = bm + wm + (mt << 4) + mrow;
            int c = bn + wn + (nt << 3) + ncol;
            float b0 = bias[c], b1 = bias[c+1];
            float v0 = acc[mt][nt][0] + b0, v1 = acc[mt][nt][1] + b1;
            float v2 = acc[mt][nt][2] + b0, v3 = acc[mt][nt][3] + b1;
            if (MODE == 1) {
                v0 = gelu_f(v0); v1 = gelu_f(v1); v2 = gelu_f(v2); v3 = gelu_f(v3);
                __half h0 = __float2half(v0), h1 = __float2half(v1);
                __half h2 = __float2half(v2), h3 = __float2half(v3);
                *(__half2*)&Chi[(size_t)r*N + c]     = __halves2half2(h0, h1);
                *(__half2*)&Chi[(size_t)(r+8)*N + c] = __halves2half2(h2, h3);
                *(__half2*)&Clo[(size_t)r*N + c]     = __halves2half2(
                    __float2half(v0 - __half2float(h0)), __float2half(v1 - __half2float(h1)));
                *(__half2*)&Clo[(size_t)(r+8)*N + c] = __halves2half2(
                    __float2half(v2 - __half2float(h2)), __float2half(v3 - __half2float(h3)));
            } else if (MODE == 2) {
                if (qgp) {
                    *(float2*)&C2[(size_t)r*DD + c]     = make_float2(v0, v1);
                    *(float2*)&C2[(size_t)(r+8)*DD + c] = make_float2(v2, v3);
                } else if (seg <= 2) {
                    int cc = c - seg*DD;
                    size_t o0 = (size_t)r*DD + cc, o1 = (size_t)(r+8)*DD + cc;
                    __half h0 = __float2half(v0), h1 = __float2half(v1);
                    __half h2 = __float2half(v2), h3 = __float2half(v3);
                    __half2 hi0 = __halves2half2(h0, h1), hi1 = __halves2half2(h2, h3);
                    __half2 lo0 = __halves2half2(__float2half(v0 - __half2float(h0)),
                                                 __float2half(v1 - __half2float(h1)));
                    __half2 lo1 = __halves2half2(__float2half(v2 - __half2float(h2)),
                                                 __float2half(v3 - __half2float(h3)));
                    if (seg == 0) {
                        *(__half2*)&g_bqh[o0] = hi0; *(__half2*)&g_bqh[o1] = hi1;
                        *(__half2*)&g_bql[o0] = lo0; *(__half2*)&g_bql[o1] = lo1;
                    } else if (seg == 1) {
                        *(__half2*)&g_bkh[o0] = hi0; *(__half2*)&g_bkh[o1] = hi1;
                    } else {
                        *(__half2*)&g_bvh[o0] = hi0; *(__half2*)&g_bvh[o1] = hi1;
                        *(__half2*)&g_bvl[o0] = lo0; *(__half2*)&g_bvl[o1] = lo1;
                    }
                } else {
                    *(float2*)&C[(size_t)r*N + c]     = make_float2(v0, v1);
                    *(float2*)&C[(size_t)(r+8)*N + c] = make_float2(v2, v3);
                }
            } else {
                *(float2*)&C[(size_t)r*N + c]     = make_float2(v0, v1);
                *(float2*)&C[(size_t)(r+8)*N + c] = make_float2(v2, v3);
            }
        }
    }
}

// ---------------- band attention via mma: cp.async double-buffered chunks -------
#define QP 72
#define KP 72
#define BUF_BYTES (3*64*KP*2)               // 27648 per chunk buffer
#define SMEM_BAND (2*BUF_BYTES + 128)       // 55424 (klos[2][64] at tail)

__device__ __forceinline__ void band_stage(int c, int n, int b, int h, int tid,
        uint32_t bufb, unsigned char* klosb,
        const __half* __restrict__ bkh, const __half* __restrict__ bvh,
        const __half* __restrict__ bvl,
        const int* __restrict__ idxg, const unsigned char* __restrict__ klo) {
    const int kpb = n*WW + (c << 6) - WW;
    #pragma unroll
    for (int t = 0; t < 2; t++) {
        int u = tid + (t << 8);
        int row = u >> 3, c8 = (u & 7) << 3;
        int gk; bool valid;
        if (c == 12) { gk = idxg[b*GG + row]; valid = true; }
        else { gk = kpb + row; valid = (gk >= 0) && (gk < SS); }
        int gks = valid ? gk : 0;
        size_t src = (size_t)(b*SS + gks)*DD + h*DHH + c8;
        cp16z(bufb + (uint32_t)((row*KP + c8) << 1),          &bkh[src], valid);
        cp16z(bufb + (uint32_t)((64*KP + row*KP + c8) << 1),  &bvh[src], valid);
        cp16z(bufb + (uint32_t)((128*KP + row*KP + c8) << 1), &bvl[src], valid);
        if (c8 == 0) klosb[row] = (c != 12 && valid) ? klo[b*SS + gks] : 0;
    }
}

__global__ void __launch_bounds__(256) band_mma_k(
        const __half* __restrict__ bqh, const __half* __restrict__ bql,
        const __half* __restrict__ bkh,
        const __half* __restrict__ bvh, const __half* __restrict__ bvl,
        const int* __restrict__ idxg, const unsigned char* __restrict__ klo,
        __half* __restrict__ ohi, __half* __restrict__ olo) {
    extern __shared__ __half smh[];
    unsigned char* klosA = (unsigned char*)smh + 2*BUF_BYTES;
    const uint32_t smb = smem_u32(smh);
    const int qt = blockIdx.x, bh = blockIdx.y;
    const int b = bh / HH, h = bh % HH;
    const int n = qt >> 1, r0 = (qt & 1) << 7;
    const int tid = threadIdx.x, w = tid >> 5, lane = tid & 31;
    const int t0 = n*WW + r0;
    const int lrow = lane & 15, lcol = (lane >> 4) << 3;

    // stage Q (one-shot; region aliased by chunk buffers afterwards)
    #pragma unroll
    for (int t = 0; t < 4; t++) {
        int u = tid + (t << 8);
        int row = u >> 3, c8 = (u & 7) << 3;
        size_t src = (size_t)(b*SS + t0 + row)*DD + h*DHH + c8;
        *(uint4*)&smh[row*QP + c8]          = *(const uint4*)&bqh[src];
        *(uint4*)&smh[128*QP + row*QP + c8] = *(const uint4*)&bql[src];
    }
    __syncthreads();
    uint32_t afh[4][4], afl[4][4];
    #pragma unroll
    for (int ks = 0; ks < 4; ks++) {
        uint32_t a0 = smb + (uint32_t)(((w*16 + lrow)*QP + ks*16 + lcol) << 1);
        ldmat4(afh[ks][0], afh[ks][1], afh[ks][2], afh[ks][3], a0);
        ldmat4(afl[ks][0], afl[ks][1], afl[ks][2], afl[ks][3], a0 + (uint32_t)(128*QP*2));
    }
    __syncthreads();    // all warps done reading Q region before prefetch overwrites

    float acco[8][4];
    #pragma unroll
    for (int nt = 0; nt < 8; nt++)
        #pragma unroll
        for (int r = 0; r < 4; r++) acco[nt][r] = 0.f;
    float m0 = -INFINITY, m1 = -INFINITY, l0 = 0.f, l1 = 0.f;
    const int qw0 = r0 + w*16 + (lane >> 2);
    const int cstart = (qt & 1) << 1;

    // prefetch chunk 0 into buf 0
    band_stage(cstart, n, b, h, tid, smb, klosA, bkh, bvh, bvl, idxg, klo);
    CP_COMMIT();

    for (int cc = 0; cc <= 10; cc++) {
        const int c = (cc < 10) ? (cstart + cc) : 12;
        const int kpb = n*WW + (c << 6) - WW;
        __syncthreads();   // previous compute done before overwriting its buffer
        if (cc < 10) {
            const int c2 = (cc + 1 < 10) ? (cstart + cc + 1) : 12;
            const int bs = (cc + 1) & 1;
            band_stage(c2, n, b, h, tid, smb + bs*BUF_BYTES, klosA + bs*64,
                       bkh, bvh, bvl, idxg, klo);
        }
        CP_COMMIT();
        CP_WAIT1();
        __syncthreads();
        const uint32_t bufb = smb + (cc & 1)*BUF_BYTES;
        unsigned char* klos = klosA + (cc & 1)*64;

        float accs[8][4];
        #pragma unroll
        for (int nt = 0; nt < 8; nt++)
            #pragma unroll
            for (int r = 0; r < 4; r++) accs[nt][r] = 0.f;
        #pragma unroll
        for (int ks = 0; ks < 4; ks++) {
            uint32_t bf[8][2];
            #pragma unroll
            for (int np = 0; np < 4; np++) {
                uint32_t q0, q1, q2, q3;
                ldmat4(q0, q1, q2, q3,
                       bufb + (uint32_t)(((np*16 + lrow)*KP + ks*16 + lcol) << 1));
                bf[2*np][0] = q0; bf[2*np+1][0] = q1;
                bf[2*np][1] = q2; bf[2*np+1][1] = q3;
            }
            #pragma unroll
            for (int nt = 0; nt < 8; nt++) mma16816(accs[nt], afh[ks], bf[nt]);
            #pragma unroll
            for (int nt = 0; nt < 8; nt++) mma16816(accs[nt], afl[ks], bf[nt]);
        }
        float cm0 = -3.4e38f, cm1 = -3.4e38f;
        #pragma unroll
        for (int nt = 0; nt < 8; nt++) {
            int col0 = nt*8 + ((lane & 3) << 1);
            #pragma unroll
            for (int e = 0; e < 2; e++) {
                int col = col0 + e;
                float s0 = accs[nt][e]   * 0.125f;
                float s1 = accs[nt][2+e] * 0.125f;
                if (c != 12) {
                    int gk = kpb + col;
                    bool okc = (gk >= 0) && (gk < SS) && klos[col];
                    int j = (c << 6) + col;
                    if (!(okc && j >= qw0     && j <= qw0 + 512))     s0 = NEGV;
                    if (!(okc && j >= qw0 + 8 && j <= qw0 + 8 + 512)) s1 = NEGV;
                }
                accs[nt][e] = s0; accs[nt][2+e] = s1;
                cm0 = fmaxf(cm0, s0); cm1 = fmaxf(cm1, s1);
            }
        }
        cm0 = fmaxf(cm0, __shfl_xor_sync(0xffffffffu, cm0, 1));
        cm0 = fmaxf(cm0, __shfl_xor_sync(0xffffffffu, cm0, 2));
        cm1 = fmaxf(cm1, __shfl_xor_sync(0xffffffffu, cm1, 1));
        cm1 = fmaxf(cm1, __shfl_xor_sync(0xffffffffu, cm1, 2));
        float mn0 = fmaxf(m0, cm0), mn1 = fmaxf(m1, cm1);
        float rs0 = __expf(m0 - mn0), rs1 = __expf(m1 - mn1);
        uint32_t pfu[4][4];
        float ls0 = 0.f, ls1 = 0.f;
        #pragma unroll
        for (int t = 0; t < 4; t++) {
            int nA = 2*t, nB = 2*t + 1;
            float e00 = __expf(accs[nA][0] - mn0), e01 = __expf(accs[nA][1] - mn0);
            float e10 = __expf(accs[nA][2] - mn1), e11 = __expf(accs[nA][3] - mn1);
            float f00 = __expf(accs[nB][0] - mn0), f01 = __expf(accs[nB][1] - mn0);
            float f10 = __expf(accs[nB][2] - mn1), f11 = __expf(accs[nB][3] - mn1);
            ls0 += e00 + e01 + f00 + f01;
            ls1 += e10 + e11 + f10 + f11;
            pfu[t][0] = packh2(e00, e01);
            pfu[t][1] = packh2(e10, e11);
            pfu[t][2] = packh2(f00, f01);
            pfu[t][3] = packh2(f10, f11);
        }
        ls0 += __shfl_xor_sync(0xffffffffu, ls0, 1);
        ls0 += __shfl_xor_sync(0xffffffffu, ls0, 2);
        ls1 += __shfl_xor_sync(0xffffffffu, ls1, 1);
        ls1 += __shfl_xor_sync(0xffffffffu, ls1, 2);
        l0 = l0*rs0 + ls0; l1 = l1*rs1 + ls1;
        m0 = mn0; m1 = mn1;
        #pragma unroll
        for (int nt = 0; nt < 8; nt++) {
            acco[nt][0] *= rs0; acco[nt][1] *= rs0;
            acco[nt][2] *= rs1; acco[nt][3] *= rs1;
        }
        #pragma unroll
        for (int ks = 0; ks < 4; ks++) {
            uint32_t bv[8][2], bw[8][2];
            #pragma unroll
            for (int dt = 0; dt < 4; dt++) {
                uint32_t q0, q1, q2, q3;
                uint32_t ad = bufb + (uint32_t)((64*KP + (ks*16 + lrow)*KP + dt*16 + lcol) << 1);
                ldmat4t(q0, q1, q2, q3, ad);
                bv[2*dt][0] = q0; bv[2*dt][1] = q1;
                bv[2*dt+1][0] = q2; bv[2*dt+1][1] = q3;
                ldmat4t(q0, q1, q2, q3, ad + (uint32_t)(64*KP*2));
                bw[2*dt][0] = q0; bw[2*dt][1] = q1;
                bw[2*dt+1][0] = q2; bw[2*dt+1][1] = q3;
            }
            #pragma unroll
            for (int nt = 0; nt < 8; nt++) mma16816(acco[nt], pfu[ks], bv[nt]);
            #pragma unroll
            for (int nt = 0; nt < 8; nt++) mma16816(acco[nt], pfu[ks], bw[nt]);
        }
    }
    float i0 = 1.f / l0, i1 = 1.f / l1;
    int grow = b*SS + t0 + w*16 + (lane >> 2);
    #pragma unroll
    for (int nt = 0; nt < 8; nt++) {
        int col = h*DHH + nt*8 + ((lane & 3) << 1);
        float v0 = acco[nt][0]*i0, v1 = acco[nt][1]*i0;
        float v2 = acco[nt][2]*i1, v3 = acco[nt][3]*i1;
        __half h0 = __float2half(v0), h1 = __float2half(v1);
        __half h2 = __float2half(v2), h3 = __float2half(v3);
        *(__half2*)&ohi[(size_t)grow*DD + col]     = __halves2half2(h0, h1);
        *(__half2*)&ohi[(size_t)(grow+8)*DD + col] = __halves2half2(h2, h3);
        *(__half2*)&olo[(size_t)grow*DD + col]     = __halves2half2(
            __float2half(v0 - __half2float(h0)), __float2half(v1 - __half2float(h1)));
        *(__half2*)&olo[(size_t)(grow+8)*DD + col] = __halves2half2(
            __float2half(v2 - __half2float(h2)), __float2half(v3 - __half2float(h3)));
    }
}

// ---------------- global attention: segmented partials ----------------
#define KSP 68
#define SMEM_GLOB ((2*128*KSP + 64*132) * 4)

__global__ void __launch_bounds__(256, 1) glob_part_k(
        const float* __restrict__ qg, const float* __restrict__ qkv,
        const int* __restrict__ am, float* __restrict__ pacc, float* __restrict__ pml) {
    extern __shared__ float sm[];
    float* Ks = sm;
    float* Vs = sm + 128*KSP;
    float* ps = sm + 2*128*KSP;
    int seg = blockIdx.x;
    int bh = blockIdx.y, b = bh / HH, h = bh % HH;
    int tid = threadIdx.x;
    int g = tid >> 2, part = tid & 3;

    float qv[64];
    const float4* qp = (const float4*)(qg + (size_t)(b*GG+g)*DD + h*DHH);
    #pragma unroll
    for (int d4 = 0; d4 < 16; d4++) {
        float4 t = qp[d4];
        qv[4*d4] = t.x; qv[4*d4+1] = t.y; qv[4*d4+2] = t.z; qv[4*d4+3] = t.w;
    }
    float acc[16];
    #pragma unroll
    for (int i = 0; i < 16; i++) acc[i] = 0.f;
    float mrow = -INFINITY, lrow = 0.f;

    for (int c = 0; c < SEGS/128; c++) {
        int s0 = seg*SEGS + c*128;
        __syncthreads();
        #pragma unroll
        for (int t = 0; t < 8; t++) {
            int idx = tid + (t << 8);
            int row = idx >> 4, c4 = idx & 15;
            const float* src = qkv + (size_t)(b*SS + s0 + row)*QS + h*DHH + (c4 << 2);
            *(float4*)&Ks[row*KSP + (c4 << 2)] = *(const float4*)(src + 3*DD);
            *(float4*)&Vs[row*KSP + (c4 << 2)] = *(const float4*)(src + 4*DD);
        }
        __syncthreads();
        float es[32];
        float cmax = -INFINITY;
        #pragma unroll 4
        for (int i = 0; i < 32; i++) {
            int kk = (i << 2) + part;
            const float4* kr = (const float4*)(Ks + kk*KSP);
            float dot = 0.f;
            #pragma unroll
            for (int d4 = 0; d4 < 16; d4++) {
                float4 kv = kr[d4];
                dot += qv[4*d4]*kv.x + qv[4*d4+1]*kv.y + qv[4*d4+2]*kv.z + qv[4*d4+3]*kv.w;
            }
            float val = (am[b*SS + s0 + kk] != 0) ? dot*0.125f : NEGV;
            es[i] = val; cmax = fmaxf(cmax, val);
        }
        cmax = fmaxf(cmax, __shfl_xor_sync(0xffffffffu, cmax, 1));
        cmax = fmaxf(cmax, __shfl_xor_sync(0xffffffffu, cmax, 2));
        float mnew = fmaxf(mrow, cmax);
        float rs = __expf(mrow - mnew);
        float lsum = 0.f;
        #pragma unroll 4
        for (int i = 0; i < 32; i++) {
            float e = __expf(es[i] - mnew);
            ps[g*132 + (i << 2) + part] = e;
            lsum += e;
        }
        lsum += __shfl_xor_sync(0xffffffffu, lsum, 1);
        lsum += __shfl_xor_sync(0xffffffffu, lsum, 2);
        lrow = lrow*rs + lsum;
        #pragma unroll
        for (int i = 0; i < 16; i++) acc[i] *= rs;
        mrow = mnew;
        __syncthreads();
        for (int kk = 0; kk < 128; kk++) {
            float e = ps[g*132 + kk];
            const float4* vr = (const float4*)(Vs + kk*KSP + (part << 4));
            #pragma unroll
            for (int i4 = 0; i4 < 4; i4++) {
                float4 vv = vr[i4];
                acc[4*i4]   += e*vv.x; acc[4*i4+1] += e*vv.y;
                acc[4*i4+2] += e*vv.z; acc[4*i4+3] += e*vv.w;
            }
        }
    }
    size_t pb = ((size_t)(seg*BH + bh)*GG + g);
    float4* pa = (float4*)(pacc + pb*64 + (part << 4));
    #pragma unroll
    for (int i4 = 0; i4 < 4; i4++)
        pa[i4] = make_float4(acc[4*i4], acc[4*i4+1], acc[4*i4+2], acc[4*i4+3]);
    if (part == 0) { pml[pb*2] = mrow; pml[pb*2+1] = lrow; }
}

// combine + scatter (split) fused
__global__ void glob_comb_scat_k(const float* __restrict__ pacc, const float* __restrict__ pml,
                                 const int* __restrict__ idxg,
                                 __half* __restrict__ xhi, __half* __restrict__ xlo) {
    int bh = blockIdx.x, b = bh / HH, h = bh % HH;
    int tid = threadIdx.x;
    int g = tid >> 2, part = tid & 3;
    float ms[NSEG], ls[NSEG];
    float M = -INFINITY;
    #pragma unroll
    for (int s = 0; s < NSEG; s++) {
        size_t pb = ((size_t)(s*BH + bh)*GG + g);
        ms[s] = pml[pb*2]; ls[s] = pml[pb*2+1];
        M = fmaxf(M, ms[s]);
    }
    float L = 0.f;
    float acc[16];
    #pragma unroll
    for (int i = 0; i < 16; i++) acc[i] = 0.f;
    #pragma unroll
    for (int s = 0; s < NSEG; s++) {
        float wgt = __expf(ms[s] - M);
        L += ls[s]*wgt;
        size_t pb = ((size_t)(s*BH + bh)*GG + g);
        const float4* pa = (const float4*)(pacc + pb*64 + (part << 4));
        #pragma unroll
        for (int i4 = 0; i4 < 4; i4++) {
            float4 v = pa[i4];
            acc[4*i4]   += wgt*v.x; acc[4*i4+1] += wgt*v.y;
            acc[4*i4+2] += wgt*v.z; acc[4*i4+3] += wgt*v.w;
        }
    }
    float inv = 1.f / L;
    int dst = idxg[b*GG + g];
    size_t obase = (size_t)(b*SS + dst)*DD + h*DHH + (part << 4);
    #pragma unroll
    for (int i = 0; i < 16; i += 2) {
        float v0 = acc[i]*inv, v1 = acc[i+1]*inv;
        __half h0 = __float2half(v0), h1 = __float2half(v1);
        *(__half2*)&xhi[obase + i] = __halves2half2(h0, h1);
        *(__half2*)&xlo[obase + i] = __halves2half2(
            __float2half(v0 - __half2float(h0)), __float2half(v1 - __half2float(h1)));
    }
}

// ---------------- gather (split) ----------------
__global__ void gather_split_k(const float* __restrict__ x, const int* __restrict__ idxg,
                               __half* __restrict__ xghi, __half* __restrict__ xglo) {
    int r = blockIdx.x;
    int b = r / GG;
    int src = idxg[r];
    for (int d = threadIdx.x; d < DD; d += blockDim.x) {
        float v = x[((size_t)(b*SS+src))*DD + d];
        __half h = __float2half(v);
        xghi[(size_t)r*DD + d] = h;
        xglo[(size_t)r*DD + d] = __float2half(v - __half2float(h));
    }
}

// ---------------- classifier ----------------
__global__ void classify_k(const float* __restrict__ x, const float* __restrict__ Wc,
                           const float* __restrict__ bc, const int* __restrict__ lo_p,
                           const int* __restrict__ ro_p, float* __restrict__ out, int nrows) {
    int r = blockIdx.x;
    int lo = *lo_p, ro = *ro_p;
    int per_b = 63 - lo - ro;
    if (per_b <= 0) per_b = 1;
    int b = r / per_b, t = lo + (r - b*per_b);
    const float* row = x + ((size_t)(b*SS + t))*DD;
    float p[7];
    #pragma unroll
    for (int c = 0; c < 7; c++) p[c] = 0.f;
    for (int d = threadIdx.x; d < DD; d += 256) {
        float xv = row[d];
        #pragma unroll
        for (int c = 0; c < 7; c++) p[c] += xv * Wc[d*7 + c];
    }
    #pragma unroll
    for (int c = 0; c < 7; c++) {
        float tot = blk_sum(p[c]);
        if (threadIdx.x == 0) out[r*7 + c] = tot + bc[c];
    }
}

// ---------------- launch ----------------
extern "C" void kernel_launch(void* const* d_in, const int* in_sizes, int n_in,
                              void* d_out, int out_size) {
    const float* emb_tok = (const float*)d_in[0];
    const float* emb_pos = (const float*)d_in[1];
    const float* ln_e_s  = (const float*)d_in[2];
    const float* ln_e_b  = (const float*)d_in[3];
    const float* Wq  = (const float*)d_in[4];
    const float* bq  = (const float*)d_in[5];
    const float* Wk  = (const float*)d_in[6];
    const float* bk  = (const float*)d_in[7];
    const float* Wv  = (const float*)d_in[8];
    const float* bv  = (const float*)d_in[9];
    const float* Wqg = (const float*)d_in[10];
    const float* bqg = (const float*)d_in[11];
    const float* Wkg = (const float*)d_in[12];
    const float* bkg = (const float*)d_in[13];
    const float* Wvg = (const float*)d_in[14];
    const float* bvg = (const float*)d_in[15];
    const float* Wo  = (const float*)d_in[16];
    const float* bo  = (const float*)d_in[17];
    const float* ln1_s = (const float*)d_in[18];
    const float* ln1_b = (const float*)d_in[19];
    const float* Wf1 = (const float*)d_in[20];
    const float* bf1 = (const float*)d_in[21];
    const float* Wf2 = (const float*)d_in[22];
    const float* bf2 = (const float*)d_in[23];
    const float* ln2_s = (const float*)d_in[24];
    const float* ln2_b = (const float*)d_in[25];
    const float* Wc  = (const float*)d_in[26];
    const float* bc  = (const float*)d_in[27];
    const int* input_ids = (const int*)d_in[28];
    const int* attn_mask = (const int*)d_in[29];
    const int* lo_p = (const int*)d_in[30];
    const int* ro_p = (const int*)d_in[31];
    float* out = (float*)d_out;

    float *x, *qkv, *tmp, *qg, *bcat, *pacc, *pml;
    int* idxg; unsigned char* klo;
    __half *w, *ahi, *alo, *xhi, *xlo, *xghi, *xglo;
    __half *bqh, *bql, *bkh, *bvh, *bvl;
    cudaGetSymbolAddress((void**)&x,    g_x);
    cudaGetSymbolAddress((void**)&qkv,  g_qkv);
    cudaGetSymbolAddress((void**)&tmp,  g_tmp);
    cudaGetSymbolAddress((void**)&qg,   g_qg);
    cudaGetSymbolAddress((void**)&bcat, g_bcat);
    cudaGetSymbolAddress((void**)&pacc, g_pacc);
    cudaGetSymbolAddress((void**)&pml,  g_pml);
    cudaGetSymbolAddress((void**)&idxg, g_idxg);
    cudaGetSymbolAddress((void**)&klo,  g_klo);
    cudaGetSymbolAddress((void**)&w,    g_w);
    cudaGetSymbolAddress((void**)&ahi,  g_ahi);
    cudaGetSymbolAddress((void**)&alo,  g_alo);
    cudaGetSymbolAddress((void**)&xhi,  g_xhi);
    cudaGetSymbolAddress((void**)&xlo,  g_xlo);
    cudaGetSymbolAddress((void**)&xghi, g_xghi);
    cudaGetSymbolAddress((void**)&xglo, g_xglo);
    cudaGetSymbolAddress((void**)&bqh,  g_bqh);
    cudaGetSymbolAddress((void**)&bql,  g_bql);
    cudaGetSymbolAddress((void**)&bkh,  g_bkh);
    cudaGetSymbolAddress((void**)&bvh,  g_bvh);
    cudaGetSymbolAddress((void**)&bvl,  g_bvl);

    cudaFuncSetAttribute(tgemm_k<0>, cudaFuncAttributeMaxDynamicSharedMemorySize, SMEM_GEMM);
    cudaFuncSetAttribute(tgemm_k<1>, cudaFuncAttributeMaxDynamicSharedMemorySize, SMEM_GEMM);
    cudaFuncSetAttribute(tgemm_k<2>, cudaFuncAttributeMaxDynamicSharedMemorySize, SMEM_GEMM);
    cudaFuncSetAttribute(band_mma_k, cudaFuncAttributeMaxDynamicSharedMemorySize, SMEM_BAND);
    cudaFuncSetAttribute(glob_part_k, cudaFuncAttributeMaxDynamicSharedMemorySize, SMEM_GLOB);

    prep_k<<<BB, 256>>>(input_ids, attn_mask, idxg, klo);
    embed_ln_k<<<BS, 256>>>(input_ids, emb_tok, emb_pos, ln_e_s, ln_e_b, x, xhi, xlo);

    dim3 wb(32, 8);
    for (int l = 0; l < LL; l++) {
        size_t base = (size_t)l * LWOFF;
        wsplit_t_k<<<dim3(DD/32, DD/32), wb>>>(Wq  + (size_t)l*DD*DD, w+base+OFF_Q,  DD, DD);
        wsplit_t_k<<<dim3(DD/32, DD/32), wb>>>(Wk  + (size_t)l*DD*DD, w+base+OFF_K,  DD, DD);
        wsplit_t_k<<<dim3(DD/32, DD/32), wb>>>(Wv  + (size_t)l*DD*DD, w+base+OFF_V,  DD, DD);
        wsplit_t_k<<<dim3(DD/32, DD/32), wb>>>(Wkg + (size_t)l*DD*DD, w+base+OFF_KG, DD, DD);
        wsplit_t_k<<<dim3(DD/32, DD/32), wb>>>(Wvg + (size_t)l*DD*DD, w+base+OFF_VG, DD, DD);
        wsplit_t_k<<<dim3(DD/32, DD/32), wb>>>(Wqg + (size_t)l*DD*DD, w+base+OFF_QG, DD, DD);
        wsplit_t_k<<<dim3(DD/32, DD/32), wb>>>(Wo  + (size_t)l*DD*DD, w+base+OFF_O,  DD, DD);
        wsplit_t_k<<<dim3(FFN/32, DD/32), wb>>>(Wf1 + (size_t)l*DD*FFN, w+base+OFF_F1, DD, FFN);
        wsplit_t_k<<<dim3(DD/32, FFN/32), wb>>>(Wf2 + (size_t)l*FFN*DD, w+base+OFF_F2, FFN, DD);
        bcat_k<<<(QS+255)/256, 256>>>(bq + l*DD, bk + l*DD, bv + l*DD, bkg + l*DD, bvg + l*DD,
                                      bcat + l*QS);
    }

    dim3 gTqkv(QS/128, BS/128 + 1);
    dim3 gT(DD/128, BS/128);
    dim3 gT1(FFN/128, BS/128);
    dim3 gBandM(SS/128, BH);
    dim3 gGlobP(NSEG, BH);

    for (int l = 0; l < LL; l++) {
        size_t base = (size_t)l * LWOFF;
        const float* bqg_l = bqg + l*DD;
        const float* bo_l  = bo  + l*DD;
        const float* bf1_l = bf1 + l*FFN; const float* bf2_l = bf2 + l*DD;

        gather_split_k<<<BB*GG, 256>>>(x, idxg, xghi, xglo);
        tgemm_k<2><<<gTqkv, 256, SMEM_GEMM>>>(xhi, xlo, w+base+OFF_Q,
                                              bcat + l*QS, qkv, 0, 0, BS, QS, DD,
                                              xghi, xglo, w+base+OFF_QG, bqg_l, qg);

        band_mma_k<<<gBandM, 256, SMEM_BAND>>>(bqh, bql, bkh, bvh, bvl, idxg, klo, xhi, xlo);

        glob_part_k<<<gGlobP, 256, SMEM_GLOB>>>(qg, qkv, attn_mask, pacc, pml);
        glob_comb_scat_k<<<BH, 256>>>(pacc, pml, idxg, xhi, xlo);

        tgemm_k<0><<<gT, 256, SMEM_GEMM>>>(xhi, xlo, w+base+OFF_O,
                                           bo_l, tmp, 0, 0, BS, DD, DD,
                                           0, 0, 0, 0, 0);
        add_ln_k<<<BS, 256>>>(x, tmp, ln1_s + l*DD, ln1_b + l*DD, xhi, xlo);

        tgemm_k<1><<<gT1, 256, SMEM_GEMM>>>(xhi, xlo, w+base+OFF_F1,
                                            bf1_l, 0, ahi, alo, BS, FFN, DD,
                                            0, 0, 0, 0, 0);
        tgemm_k<0><<<gT, 256, SMEM_GEMM>>>(ahi, alo, w+base+OFF_F2,
                                           bf2_l, tmp, 0, 0, BS, DD, FFN,
                                           0, 0, 0, 0, 0);
        add_ln_k<<<BS, 256>>>(x, tmp, ln2_s + l*DD, ln2_b + l*DD, xhi, xlo);
    }

    int nrows = out_size / 7;
    classify_k<<<nrows, 256>>>(x, Wc, bc, lo_p, ro_p, out, nrows);
}

// round 16
// speedup vs baseline: 1.0427x; 1.0427x over previous
#include <cuda_runtime.h>
#include <cuda_fp16.h>
#include <cstdint>
#include <math.h>

#define BB 2
#define SS 4096
#define DD 768
#define HH 12
#define LL 2
#define DHH 64
#define WW 256
#define GG 64
#define FFN 3072
#define SEPID 2
#define NEGV -1000000000.0f
#define BS (BB*SS)
#define QS (5*DD)
#define NSEG 8
#define SEGS (SS/NSEG)
#define BH (BB*HH)

#define WSZ_DD (DD*DD)
#define OFF_Q  0
#define OFF_K  (1*WSZ_DD)
#define OFF_V  (2*WSZ_DD)
#define OFF_KG (3*WSZ_DD)
#define OFF_VG (4*WSZ_DD)
#define OFF_QG (5*WSZ_DD)
#define OFF_O  (6*WSZ_DD)
#define OFF_F1 (7*WSZ_DD)
#define OFF_F2 (7*WSZ_DD + DD*FFN)
#define LWOFF  (7*WSZ_DD + 2*DD*FFN)

// merged weight-conversion tiling
#define NT_DD 576                   // (DD/32)*(DD/32)
#define NT_FF 2304                  // (FFN/32)*(DD/32)
#define TILES_DD (14*NT_DD)         // 8064
#define TILES_W  (TILES_DD + 4*NT_FF)   // 17280
#define BCAT_T   (QS/256)           // 15 per layer
#define TILES_ALL (TILES_W + 2*BCAT_T)

// ---------------- scratch ----------------
__device__ float g_x[BS*DD];
__device__ float g_qkv[(size_t)BS*QS];
__device__ float g_tmp[BS*DD];
__device__ float g_qg[BB*GG*DD];
__device__ float g_bcat[2*QS];
__device__ float g_pacc[NSEG*BH*GG*64];
__device__ float g_pml[NSEG*BH*GG*2];
__device__ int   g_idxg[BB*GG];
__device__ unsigned char g_klo[BS];

__device__ __align__(16) __half g_w[2*LWOFF];
__device__ __align__(16) __half g_ahi[BS*FFN];
__device__ __align__(16) __half g_alo[BS*FFN];
__device__ __align__(16) __half g_xhi[BS*DD];
__device__ __align__(16) __half g_xlo[BS*DD];
__device__ __align__(16) __half g_xghi[BB*GG*DD];
__device__ __align__(16) __half g_xglo[BB*GG*DD];
__device__ __align__(16) __half g_bqh[BS*DD];
__device__ __align__(16) __half g_bql[BS*DD];
__device__ __align__(16) __half g_bkh[BS*DD];
__device__ __align__(16) __half g_bvh[BS*DD];
__device__ __align__(16) __half g_bvl[BS*DD];

// ---------------- helpers ----------------
__device__ __forceinline__ uint32_t smem_u32(const void* p) {
    uint32_t a;
    asm("{ .reg .u64 t; cvta.to.shared.u64 t, %1; cvt.u32.u64 %0, t; }" : "=r"(a) : "l"(p));
    return a;
}

__device__ __forceinline__ void cp16(uint32_t dst, const void* src) {
    asm volatile("cp.async.ca.shared.global [%0], [%1], 16;" :: "r"(dst), "l"(src));
}
#define CP_COMMIT() asm volatile("cp.async.commit_group;" ::: "memory")
#define CP_WAIT2()  asm volatile("cp.async.wait_group 2;" ::: "memory")

__device__ __forceinline__ void ldmat4(uint32_t& r0, uint32_t& r1, uint32_t& r2, uint32_t& r3,
                                       uint32_t addr) {
    asm volatile("ldmatrix.sync.aligned.m8n8.x4.shared.b16 {%0,%1,%2,%3}, [%4];"
        : "=r"(r0), "=r"(r1), "=r"(r2), "=r"(r3) : "r"(addr));
}

__device__ __forceinline__ void ldmat4t(uint32_t& r0, uint32_t& r1, uint32_t& r2, uint32_t& r3,
                                        uint32_t addr) {
    asm volatile("ldmatrix.sync.aligned.m8n8.x4.trans.shared.b16 {%0,%1,%2,%3}, [%4];"
        : "=r"(r0), "=r"(r1), "=r"(r2), "=r"(r3) : "r"(addr));
}

__device__ __forceinline__ void mma16816(float* d, const uint32_t* a, const uint32_t* b) {
    asm volatile("mma.sync.aligned.m16n8k16.row.col.f32.f16.f16.f32 "
        "{%0,%1,%2,%3}, {%4,%5,%6,%7}, {%8,%9}, {%0,%1,%2,%3};"
        : "+f"(d[0]), "+f"(d[1]), "+f"(d[2]), "+f"(d[3])
        : "r"(a[0]), "r"(a[1]), "r"(a[2]), "r"(a[3]), "r"(b[0]), "r"(b[1]));
}

__device__ __forceinline__ uint32_t packh2(float a, float b) {
    __half2 h = __floats2half2_rn(a, b);
    return *(uint32_t*)&h;
}

__device__ __forceinline__ float gelu_f(float v) {
    return 0.5f*v*(1.f + tanhf(0.7978845608028654f*(v + 0.044715f*v*v*v)));
}

// ---------------- block reductions ----------------
__device__ __forceinline__ float blk_sum(float v) {
    __shared__ float sm[33];
    int lane = threadIdx.x & 31, wid = threadIdx.x >> 5;
    #pragma unroll
    for (int o = 16; o; o >>= 1) v += __shfl_xor_sync(0xffffffffu, v, o);
    if (lane == 0) sm[wid] = v;
    __syncthreads();
    if (wid == 0) {
        int nw = (blockDim.x + 31) >> 5;
        float r = (lane < nw) ? sm[lane] : 0.f;
        #pragma unroll
        for (int o = 16; o; o >>= 1) r += __shfl_xor_sync(0xffffffffu, r, o);
        if (lane == 0) sm[32] = r;
    }
    __syncthreads();
    float r = sm[32];
    __syncthreads();
    return r;
}

// ---------------- prep ----------------
__global__ void prep_k(const int* __restrict__ ids, const int* __restrict__ am,
                       int* __restrict__ idxg, unsigned char* __restrict__ klo) {
    int b = blockIdx.x;
    for (int s = threadIdx.x; s < SS; s += blockDim.x) {
        bool g = (ids[b*SS+s] == SEPID) || (s == 0);
        klo[b*SS+s] = (am[b*SS+s] != 0 && !g) ? 1 : 0;
    }
    if (threadIdx.x == 0) {
        int cnt = 0;
        for (int s = 0; s < SS && cnt < GG; s++)
            if (ids[b*SS+s] == SEPID || s == 0) idxg[b*GG + cnt++] = s;
        for (; cnt < GG; cnt++) idxg[b*GG + cnt] = 0;
    }
}

// ---------------- embedding + LN ----------------
__global__ void embed_ln_k(const int* __restrict__ ids, const float* __restrict__ etok,
                           const float* __restrict__ epos, const float* __restrict__ lns,
                           const float* __restrict__ lnb, float* __restrict__ x,
                           __half* __restrict__ xhi, __half* __restrict__ xlo) {
    int row = blockIdx.x;
    int spos = row & (SS - 1);
    int id = ids[row];
    const float* te = etok + (size_t)id * DD;
    const float* pe = epos + (size_t)spos * DD;
    float v[3]; float sum = 0.f;
    #pragma unroll
    for (int i = 0; i < 3; i++) {
        int d = threadIdx.x + i*256;
        float val = te[d] + pe[d];
        v[i] = val; sum += val;
    }
    float mean = blk_sum(sum) * (1.0f/DD);
    float sq = 0.f;
    #pragma unroll
    for (int i = 0; i < 3; i++) { float c = v[i] - mean; sq += c*c; }
    float inv = rsqrtf(blk_sum(sq) * (1.0f/DD) + 1e-5f);
    #pragma unroll
    for (int i = 0; i < 3; i++) {
        int d = threadIdx.x + i*256;
        float o = (v[i] - mean)*inv*lns[d] + lnb[d];
        x[(size_t)row*DD + d] = o;
        __half h = __float2half(o);
        xhi[(size_t)row*DD + d] = h;
        xlo[(size_t)row*DD + d] = __float2half(o - __half2float(h));
    }
}

// ---------------- residual add + LN ----------------
__global__ void add_ln_k(float* __restrict__ x, const float* __restrict__ t,
                         const float* __restrict__ lns, const float* __restrict__ lnb,
                         __half* __restrict__ xhi, __half* __restrict__ xlo) {
    int row = blockIdx.x;
    size_t base = (size_t)row * DD;
    float v[3]; float sum = 0.f;
    #pragma unroll
    for (int i = 0; i < 3; i++) {
        int d = threadIdx.x + i*256;
        float val = x[base+d] + t[base+d];
        v[i] = val; sum += val;
    }
    float mean = blk_sum(sum) * (1.0f/DD);
    float sq = 0.f;
    #pragma unroll
    for (int i = 0; i < 3; i++) { float c = v[i] - mean; sq += c*c; }
    float inv = rsqrtf(blk_sum(sq) * (1.0f/DD) + 1e-5f);
    #pragma unroll
    for (int i = 0; i < 3; i++) {
        int d = threadIdx.x + i*256;
        float o = (v[i] - mean)*inv*lns[d] + lnb[d];
        x[base+d] = o;
        __half h = __float2half(o);
        xhi[base+d] = h;
        xlo[base+d] = __float2half(o - __half2float(h));
    }
}

// ---------------- merged weight conversion + bias concat (one launch) -----------
__global__ void wsplit_all_k(
        const float* __restrict__ Wq,  const float* __restrict__ Wk,
        const float* __restrict__ Wv,  const float* __restrict__ Wkg,
        const float* __restrict__ Wvg, const float* __restrict__ Wqg,
        const float* __restrict__ Wo,  const float* __restrict__ Wf1,
        const float* __restrict__ Wf2,
        const float* __restrict__ bq,  const float* __restrict__ bk,
        const float* __restrict__ bv,  const float* __restrict__ bkg,
        const float* __restrict__ bvg,
        __half* __restrict__ w, float* __restrict__ bcat) {
    int tile = blockIdx.x;
    int tx = threadIdx.x, ty = threadIdx.y;
    if (tile >= TILES_W) {
        int t2 = tile - TILES_W;
        int l = t2 / BCAT_T, blk = t2 - l*BCAT_T;
        int i = blk*256 + ty*32 + tx;
        int seg = i / DD, off = i - seg*DD;
        const float* src = (seg == 0) ? bq : (seg == 1) ? bk : (seg == 2) ? bv
                         : (seg == 3) ? bkg : bvg;
        bcat[l*QS + i] = src[l*DD + off];
        return;
    }
    __shared__ float t[32][33];
    const float* src; size_t doff; int K, N, lt;
    if (tile < TILES_DD) {
        int mi = tile / NT_DD; lt = tile - mi*NT_DD;
        int l = mi / 7, m = mi - l*7;
        size_t base = (size_t)l * LWOFF;
        K = DD; N = DD;
        switch (m) {
            case 0: src = Wq  + (size_t)l*DD*DD; doff = base + OFF_Q;  break;
            case 1: src = Wk  + (size_t)l*DD*DD; doff = base + OFF_K;  break;
            case 2: src = Wv  + (size_t)l*DD*DD; doff = base + OFF_V;  break;
            case 3: src = Wkg + (size_t)l*DD*DD; doff = base + OFF_KG; break;
            case 4: src = Wvg + (size_t)l*DD*DD; doff = base + OFF_VG; break;
            case 5: src = Wqg + (size_t)l*DD*DD; doff = base + OFF_QG; break;
            default: src = Wo + (size_t)l*DD*DD; doff = base + OFF_O;  break;
        }
    } else {
        int t2 = tile - TILES_DD;
        int q = t2 / NT_FF; lt = t2 - q*NT_FF;
        int l = q >> 1; int isF2 = q & 1;
        size_t base = (size_t)l * LWOFF;
        if (!isF2) { src = Wf1 + (size_t)l*DD*FFN; doff = base + OFF_F1; K = DD; N = FFN; }
        else       { src = Wf2 + (size_t)l*FFN*DD; doff = base + OFF_F2; K = FFN; N = DD; }
    }
    int ntx = N >> 5;
    int n0 = (lt % ntx) << 5, k0 = (lt / ntx) << 5;
    #pragma unroll
    for (int i = 0; i < 4; i++)
        t[ty+8*i][tx] = src[(size_t)(k0+ty+8*i)*N + n0 + tx];
    __syncthreads();
    __half* hi = w + doff;
    #pragma unroll
    for (int i = 0; i < 4; i++)
        hi[(size_t)(n0+ty+8*i)*K + k0 + tx] = __float2half(t[tx][ty+8*i]);
}

// ---------------- tensor-core GEMM: BK=32, cp.async 4-stage, fp16 2-pass --------
#define SPAD 40
#define STG_BYTES (128*SPAD*2)
#define SMEM_GEMM (8*STG_BYTES)

template<int MODE>
__global__ void __launch_bounds__(256, 2) tgemm_k(
        const __half* __restrict__ Ahi_, const __half* __restrict__ Alo_,
        const __half* __restrict__ B_,
        const float* __restrict__ bias_, float* __restrict__ C,
        __half* __restrict__ Chi, __half* __restrict__ Clo,
        int M, int N_, int K,
        const __half* A2hi, const __half* A2lo, const __half* B2,
        const float* bias2, float* C2) {
    extern __shared__ char smem[];
    const uint32_t sm0 = smem_u32(smem);
    const bool qgp = (MODE == 2) && ((int)blockIdx.y == (BS >> 7));
    if (qgp && blockIdx.x >= DD/128) return;
    const __half* Ahi = qgp ? A2hi : Ahi_;
    const __half* Alo = qgp ? A2lo : Alo_;
    const __half* B   = qgp ? B2   : B_;
    const float* bias = qgp ? bias2 : bias_;
    const int N = qgp ? DD : N_;
    const int bn = blockIdx.x << 7;
    const int bm = qgp ? 0 : (blockIdx.y << 7);
    const int tid = threadIdx.x, wid = tid >> 5, lane = tid & 31;
    const int wm = (wid >> 2) << 6;
    const int wn = (wid & 3) << 5;

    float acc[4][4][4];
    #pragma unroll
    for (int i = 0; i < 4; i++)
        #pragma unroll
        for (int j = 0; j < 4; j++)
            #pragma unroll
            for (int r = 0; r < 4; r++) acc[i][j][r] = 0.f;

    const int KC = K >> 5;
    const int total = 2 * KC;
    const __half* Aps[2] = {Ahi, Alo};

    const int r0 = tid >> 2, c0 = (tid & 3) << 3;
    const int r1 = r0 + 64;
    const uint32_t dA0 = (uint32_t)((r0*SPAD + c0) << 1);
    const uint32_t dA1 = (uint32_t)((r1*SPAD + c0) << 1);

    const int lrow = lane & 15, lcol = (lane >> 4) << 3;
    const uint32_t offA = (uint32_t)(((wm + lrow) * SPAD + lcol) << 1);
    const uint32_t offB = (uint32_t)(((wn + lrow) * SPAD + lcol) << 1) + 4*STG_BYTES;

    #pragma unroll
    for (int p = 0; p < 3; p++) {
        const int pass = (p < KC) ? 0 : 1;
        const int kc = p - pass*KC;
        const __half* Ap = Aps[pass];
        const int kb = kc << 5;
        const uint32_t sa = sm0 + p*STG_BYTES;
        const uint32_t sb = sm0 + 4*STG_BYTES + p*STG_BYTES;
        cp16(sa + dA0, Ap + (size_t)(bm + r0)*K + kb + c0);
        cp16(sa + dA1, Ap + (size_t)(bm + r1)*K + kb + c0);
        cp16(sb + dA0, B + (size_t)(bn + r0)*K + kb + c0);
        cp16(sb + dA1, B + (size_t)(bn + r1)*K + kb + c0);
        CP_COMMIT();
    }

    for (int s = 0; s < total; s++) {
        CP_WAIT2();
        __syncthreads();
        const int p = s + 3;
        if (p < total) {
            const int pass = (p < KC) ? 0 : 1;
            const int kc = p - pass*KC;
            const __half* Ap = Aps[pass];
            const int kb = kc << 5;
            const int st2 = p & 3;
            const uint32_t sa = sm0 + st2*STG_BYTES;
            const uint32_t sb = sm0 + 4*STG_BYTES + st2*STG_BYTES;
            cp16(sa + dA0, Ap + (size_t)(bm + r0)*K + kb + c0);
            cp16(sa + dA1, Ap + (size_t)(bm + r1)*K + kb + c0);
            cp16(sb + dA0, B + (size_t)(bn + r0)*K + kb + c0);
            cp16(sb + dA1, B + (size_t)(bn + r1)*K + kb + c0);
        }
        CP_COMMIT();
        const int stg = s & 3;
        const uint32_t abase = sm0 + stg*STG_BYTES + offA;
        const uint32_t bbase = sm0 + stg*STG_BYTES + offB;
        #pragma unroll
        for (int ks = 0; ks < 2; ks++) {
            uint32_t af[4][4], bf[4][2];
            #pragma unroll
            for (int mt = 0; mt < 4; mt++)
                ldmat4(af[mt][0], af[mt][1], af[mt][2], af[mt][3],
                       abase + (uint32_t)(((mt << 4) * SPAD + (ks << 4)) << 1));
            #pragma unroll
            for (int np = 0; np < 2; np++) {
                uint32_t m0, m1, m2, m3;
                ldmat4(m0, m1, m2, m3,
                       bbase + (uint32_t)(((np << 4) * SPAD + (ks << 4)) << 1));
                bf[2*np][0] = m0; bf[2*np+1][0] = m1;
                bf[2*np][1] = m2; bf[2*np+1][1] = m3;
            }
            #pragma unroll
            for (int mt = 0; mt < 4; mt++)
                #pragma unroll
                for (int nt = 0; nt < 4; nt++)
                    mma16816(acc[mt][nt], af[mt], bf[nt]);
        }
    }

    const int mrow = lane >> 2, ncol = (lane & 3) << 1;
    const int seg = bn / DD;
    #pragma unroll
    for (int mt = 0; mt < 4; mt++) {
        #pragma unroll
        for (int nt = 0; nt < 4; nt++) {
            int r = bm + wm + (mt << 4) + mrow;
            int c = bn + wn + (nt << 3) + ncol;
            float b0 = bias[c], b1 = bias[c+1];
            float v0 = acc[mt][nt][0] + b0, v1 = acc[mt][nt][1] + b1;
            float v2 = acc[mt][nt][2] + b0, v3 = acc[mt][nt][3] + b1;
            if (MODE == 1) {
                v0 = gelu_f(v0); v1 = gelu_f(v1); v2 = gelu_f(v2); v3 = gelu_f(v3);
                __half h0 = __float2half(v0), h1 = __float2half(v1);
                __half h2 = __float2half(v2), h3 = __float2half(v3);
                *(__half2*)&Chi[(size_t)r*N + c]     = __halves2half2(h0, h1);
                *(__half2*)&Chi[(size_t)(r+8)*N + c] = __halves2half2(h2, h3);
                *(__half2*)&Clo[(size_t)r*N + c]     = __halves2half2(
                    __float2half(v0 - __half2float(h0)), __float2half(v1 - __half2float(h1)));
                *(__half2*)&Clo[(size_t)(r+8)*N + c] = __halves2half2(
                    __float2half(v2 - __half2float(h2)), __float2half(v3 - __half2float(h3)));
            } else if (MODE == 2) {
                if (qgp) {
                    *(float2*)&C2[(size_t)r*DD + c]     = make_float2(v0, v1);
                    *(float2*)&C2[(size_t)(r+8)*DD + c] = make_float2(v2, v3);
                } else if (seg <= 2) {
                    int cc = c - seg*DD;
                    size_t o0 = (size_t)r*DD + cc, o1 = (size_t)(r+8)*DD + cc;
                    __half h0 = __float2half(v0), h1 = __float2half(v1);
                    __half h2 = __float2half(v2), h3 = __float2half(v3);
                    __half2 hi0 = __halves2half2(h0, h1), hi1 = __halves2half2(h2, h3);
                    __half2 lo0 = __halves2half2(__float2half(v0 - __half2float(h0)),
                                                 __float2half(v1 - __half2float(h1)));
                    __half2 lo1 = __halves2half2(__float2half(v2 - __half2float(h2)),
                                                 __float2half(v3 - __half2float(h3)));
                    if (seg == 0) {
                        *(__half2*)&g_bqh[o0] = hi0; *(__half2*)&g_bqh[o1] = hi1;
                        *(__half2*)&g_bql[o0] = lo0; *(__half2*)&g_bql[o1] = lo1;
                    } else if (seg == 1) {
                        *(__half2*)&g_bkh[o0] = hi0; *(__half2*)&g_bkh[o1] = hi1;
                    } else {
                        *(__half2*)&g_bvh[o0] = hi0; *(__half2*)&g_bvh[o1] = hi1;
                        *(__half2*)&g_bvl[o0] = lo0; *(__half2*)&g_bvl[o1] = lo1;
                    }
                } else {
                    *(float2*)&C[(size_t)r*N + c]     = make_float2(v0, v1);
                    *(float2*)&C[(size_t)(r+8)*N + c] = make_float2(v2, v3);
                }
            } else {
                *(float2*)&C[(size_t)r*N + c]     = make_float2(v0, v1);
                *(float2*)&C[(size_t)(r+8)*N + c] = make_float2(v2, v3);
            }
        }
    }
}

// ---------------- band attention via mma (static smem, occ 2) ----------------
#define QP 72
#define KP 72

__global__ void __launch_bounds__(256) band_mma_k(
        const __half* __restrict__ bqh, const __half* __restrict__ bql,
        const __half* __restrict__ bkh,
        const __half* __restrict__ bvh, const __half* __restrict__ bvl,
        const int* __restrict__ idxg, const unsigned char* __restrict__ klo,
        __half* __restrict__ ohi, __half* __restrict__ olo) {
    __shared__ __half smh[2*128*QP];
    unsigned char* klos = (unsigned char*)(smh + 3*64*KP);
    const uint32_t smb = smem_u32(smh);
    const int qt = blockIdx.x, bh = blockIdx.y;
    const int b = bh / HH, h = bh % HH;
    const int n = qt >> 1, r0 = (qt & 1) << 7;
    const int tid = threadIdx.x, w = tid >> 5, lane = tid & 31;
    const int t0 = n*WW + r0;
    const int lrow = lane & 15, lcol = (lane >> 4) << 3;

    #pragma unroll
    for (int t = 0; t < 4; t++) {
        int u = tid + (t << 8);
        int row = u >> 3, c8 = (u & 7) << 3;
        size_t src = (size_t)(b*SS + t0 + row)*DD + h*DHH + c8;
        *(uint4*)&smh[row*QP + c8]          = *(const uint4*)&bqh[src];
        *(uint4*)&smh[128*QP + row*QP + c8] = *(const uint4*)&bql[src];
    }
    __syncthreads();
    uint32_t afh[4][4], afl[4][4];
    #pragma unroll
    for (int ks = 0; ks < 4; ks++) {
        uint32_t a0 = smb + (uint32_t)(((w*16 + lrow)*QP + ks*16 + lcol) << 1);
        ldmat4(afh[ks][0], afh[ks][1], afh[ks][2], afh[ks][3], a0);
        ldmat4(afl[ks][0], afl[ks][1], afl[ks][2], afl[ks][3], a0 + (uint32_t)(128*QP*2));
    }

    float acco[8][4];
    #pragma unroll
    for (int nt = 0; nt < 8; nt++)
        #pragma unroll
        for (int r = 0; r < 4; r++) acco[nt][r] = 0.f;
    float m0 = -INFINITY, m1 = -INFINITY, l0 = 0.f, l1 = 0.f;
    const int qw0 = r0 + w*16 + (lane >> 2);
    const int cstart = (qt & 1) << 1;

    for (int cc = 0; cc <= 10; cc++) {
        const int c = (cc < 10) ? (cstart + cc) : 12;
        const int kpb = n*WW + (c << 6) - WW;
        __syncthreads();
        #pragma unroll
        for (int t = 0; t < 2; t++) {
            int u = tid + (t << 8);
            int row = u >> 3, c8 = (u & 7) << 3;
            int gk; bool valid;
            if (c == 12) { gk = idxg[b*GG + row]; valid = true; }
            else { gk = kpb + row; valid = (gk >= 0) && (gk < SS); }
            uint4 z = make_uint4(0,0,0,0);
            size_t src = (size_t)(b*SS + gk)*DD + h*DHH + c8;
            *(uint4*)&smh[row*KP + c8]          = valid ? *(const uint4*)&bkh[src] : z;
            *(uint4*)&smh[64*KP + row*KP + c8]  = valid ? *(const uint4*)&bvh[src] : z;
            *(uint4*)&smh[128*KP + row*KP + c8] = valid ? *(const uint4*)&bvl[src] : z;
            if (c8 == 0) klos[row] = (c != 12 && valid) ? klo[b*SS + gk] : 0;
        }
        __syncthreads();

        float accs[8][4];
        #pragma unroll
        for (int nt = 0; nt < 8; nt++)
            #pragma unroll
            for (int r = 0; r < 4; r++) accs[nt][r] = 0.f;
        #pragma unroll
        for (int ks = 0; ks < 4; ks++) {
            uint32_t bf[8][2];
            #pragma unroll
            for (int np = 0; np < 4; np++) {
                uint32_t q0, q1, q2, q3;
                ldmat4(q0, q1, q2, q3,
                       smb + (uint32_t)(((np*16 + lrow)*KP + ks*16 + lcol) << 1));
                bf[2*np][0] = q0; bf[2*np+1][0] = q1;
                bf[2*np][1] = q2; bf[2*np+1][1] = q3;
            }
            #pragma unroll
            for (int nt = 0; nt < 8; nt++) mma16816(accs[nt], afh[ks], bf[nt]);
            #pragma unroll
            for (int nt = 0; nt < 8; nt++) mma16816(accs[nt], afl[ks], bf[nt]);
        }
        float cm0 = -3.4e38f, cm1 = -3.4e38f;
        #pragma unroll
        for (int nt = 0; nt < 8; nt++) {
            int col0 = nt*8 + ((lane & 3) << 1);
            #pragma unroll
            for (int e = 0; e < 2; e++) {
                int col = col0 + e;
                float s0 = accs[nt][e]   * 0.125f;
                float s1 = accs[nt][2+e] * 0.125f;
                if (c != 12) {
                    int gk = kpb + col;
                    bool okc = (gk >= 0) && (gk < SS) && klos[col];
                    int j = (c << 6) + col;
                    if (!(okc && j >= qw0     && j <= qw0 + 512))     s0 = NEGV;
                    if (!(okc && j >= qw0 + 8 && j <= qw0 + 8 + 512)) s1 = NEGV;
                }
                accs[nt][e] = s0; accs[nt][2+e] = s1;
                cm0 = fmaxf(cm0, s0); cm1 = fmaxf(cm1, s1);
            }
        }
        cm0 = fmaxf(cm0, __shfl_xor_sync(0xffffffffu, cm0, 1));
        cm0 = fmaxf(cm0, __shfl_xor_sync(0xffffffffu, cm0, 2));
        cm1 = fmaxf(cm1, __shfl_xor_sync(0xffffffffu, cm1, 1));
        cm1 = fmaxf(cm1, __shfl_xor_sync(0xffffffffu, cm1, 2));
        float mn0 = fmaxf(m0, cm0), mn1 = fmaxf(m1, cm1);
        float rs0 = __expf(m0 - mn0), rs1 = __expf(m1 - mn1);
        uint32_t pfu[4][4];
        float ls0 = 0.f, ls1 = 0.f;
        #pragma unroll
        for (int t = 0; t < 4; t++) {
            int nA = 2*t, nB = 2*t + 1;
            float e00 = __expf(accs[nA][0] - mn0), e01 = __expf(accs[nA][1] - mn0);
            float e10 = __expf(accs[nA][2] - mn1), e11 = __expf(accs[nA][3] - mn1);
            float f00 = __expf(accs[nB][0] - mn0), f01 = __expf(accs[nB][1] - mn0);
            float f10 = __expf(accs[nB][2] - mn1), f11 = __expf(accs[nB][3] - mn1);
            ls0 += e00 + e01 + f00 + f01;
            ls1 += e10 + e11 + f10 + f11;
            pfu[t][0] = packh2(e00, e01);
            pfu[t][1] = packh2(e10, e11);
            pfu[t][2] = packh2(f00, f01);
            pfu[t][3] = packh2(f10, f11);
        }
        ls0 += __shfl_xor_sync(0xffffffffu, ls0, 1);
        ls0 += __shfl_xor_sync(0xffffffffu, ls0, 2);
        ls1 += __shfl_xor_sync(0xffffffffu, ls1, 1);
        ls1 += __shfl_xor_sync(0xffffffffu, ls1, 2);
        l0 = l0*rs0 + ls0; l1 = l1*rs1 + ls1;
        m0 = mn0; m1 = mn1;
        #pragma unroll
        for (int nt = 0; nt < 8; nt++) {
            acco[nt][0] *= rs0; acco[nt][1] *= rs0;
            acco[nt][2] *= rs1; acco[nt][3] *= rs1;
        }
        #pragma unroll
        for (int ks = 0; ks < 4; ks++) {
            uint32_t bv[8][2], bw[8][2];
            #pragma unroll
            for (int dt = 0; dt < 4; dt++) {
                uint32_t q0, q1, q2, q3;
                uint32_t ad = smb + (uint32_t)((64*KP + (ks*16 + lrow)*KP + dt*16 + lcol) << 1);
                ldmat4t(q0, q1, q2, q3, ad);
                bv[2*dt][0] = q0; bv[2*dt][1] = q1;
                bv[2*dt+1][0] = q2; bv[2*dt+1][1] = q3;
                ldmat4t(q0, q1, q2, q3, ad + (uint32_t)(64*KP*2));
                bw[2*dt][0] = q0; bw[2*dt][1] = q1;
                bw[2*dt+1][0] = q2; bw[2*dt+1][1] = q3;
            }
            #pragma unroll
            for (int nt = 0; nt < 8; nt++) mma16816(acco[nt], pfu[ks], bv[nt]);
            #pragma unroll
            for (int nt = 0; nt < 8; nt++) mma16816(acco[nt], pfu[ks], bw[nt]);
        }
    }
    float i0 = 1.f / l0, i1 = 1.f / l1;
    int grow = b*SS + t0 + w*16 + (lane >> 2);
    #pragma unroll
    for (int nt = 0; nt < 8; nt++) {
        int col = h*DHH + nt*8 + ((lane & 3) << 1);
        float v0 = acco[nt][0]*i0, v1 = acco[nt][1]*i0;
        float v2 = acco[nt][2]*i1, v3 = acco[nt][3]*i1;
        __half h0 = __float2half(v0), h1 = __float2half(v1);
        __half h2 = __float2half(v2), h3 = __float2half(v3);
        *(__half2*)&ohi[(size_t)grow*DD + col]     = __halves2half2(h0, h1);
        *(__half2*)&ohi[(size_t)(grow+8)*DD + col] = __halves2half2(h2, h3);
        *(__half2*)&olo[(size_t)grow*DD + col]     = __halves2half2(
            __float2half(v0 - __half2float(h0)), __float2half(v1 - __half2float(h1)));
        *(__half2*)&olo[(size_t)(grow+8)*DD + col] = __halves2half2(
            __float2half(v2 - __half2float(h2)), __float2half(v3 - __half2float(h3)));
    }
}

// ---------------- global attention: segmented partials ----------------
#define KSP 68
#define SMEM_GLOB ((2*128*KSP + 64*132) * 4)

__global__ void __launch_bounds__(256, 1) glob_part_k(
        const float* __restrict__ qg, const float* __restrict__ qkv,
        const int* __restrict__ am, float* __restrict__ pacc, float* __restrict__ pml) {
    extern __shared__ float sm[];
    float* Ks = sm;
    float* Vs = sm + 128*KSP;
    float* ps = sm + 2*128*KSP;
    int seg = blockIdx.x;
    int bh = blockIdx.y, b = bh / HH, h = bh % HH;
    int tid = threadIdx.x;
    int g = tid >> 2, part = tid & 3;

    float qv[64];
    const float4* qp = (const float4*)(qg + (size_t)(b*GG+g)*DD + h*DHH);
    #pragma unroll
    for (int d4 = 0; d4 < 16; d4++) {
        float4 t = qp[d4];
        qv[4*d4] = t.x; qv[4*d4+1] = t.y; qv[4*d4+2] = t.z; qv[4*d4+3] = t.w;
    }
    float acc[16];
    #pragma unroll
    for (int i = 0; i < 16; i++) acc[i] = 0.f;
    float mrow = -INFINITY, lrow = 0.f;

    for (int c = 0; c < SEGS/128; c++) {
        int s0 = seg*SEGS + c*128;
        __syncthreads();
        #pragma unroll
        for (int t = 0; t < 8; t++) {
            int idx = tid + (t << 8);
            int row = idx >> 4, c4 = idx & 15;
            const float* src = qkv + (size_t)(b*SS + s0 + row)*QS + h*DHH + (c4 << 2);
            *(float4*)&Ks[row*KSP + (c4 << 2)] = *(const float4*)(src + 3*DD);
            *(float4*)&Vs[row*KSP + (c4 << 2)] = *(const float4*)(src + 4*DD);
        }
        __syncthreads();
        float es[32];
        float cmax = -INFINITY;
        #pragma unroll 4
        for (int i = 0; i < 32; i++) {
            int kk = (i << 2) + part;
            const float4* kr = (const float4*)(Ks + kk*KSP);
            float dot = 0.f;
            #pragma unroll
            for (int d4 = 0; d4 < 16; d4++) {
                float4 kv = kr[d4];
                dot += qv[4*d4]*kv.x + qv[4*d4+1]*kv.y + qv[4*d4+2]*kv.z + qv[4*d4+3]*kv.w;
            }
            float val = (am[b*SS + s0 + kk] != 0) ? dot*0.125f : NEGV;
            es[i] = val; cmax = fmaxf(cmax, val);
        }
        cmax = fmaxf(cmax, __shfl_xor_sync(0xffffffffu, cmax, 1));
        cmax = fmaxf(cmax, __shfl_xor_sync(0xffffffffu, cmax, 2));
        float mnew = fmaxf(mrow, cmax);
        float rs = __expf(mrow - mnew);
        float lsum = 0.f;
        #pragma unroll 4
        for (int i = 0; i < 32; i++) {
            float e = __expf(es[i] - mnew);
            ps[g*132 + (i << 2) + part] = e;
            lsum += e;
        }
        lsum += __shfl_xor_sync(0xffffffffu, lsum, 1);
        lsum += __shfl_xor_sync(0xffffffffu, lsum, 2);
        lrow = lrow*rs + lsum;
        #pragma unroll
        for (int i = 0; i < 16; i++) acc[i] *= rs;
        mrow = mnew;
        __syncthreads();
        for (int kk = 0; kk < 128; kk++) {
            float e = ps[g*132 + kk];
            const float4* vr = (const float4*)(Vs + kk*KSP + (part << 4));
            #pragma unroll
            for (int i4 = 0; i4 < 4; i4++) {
                float4 vv = vr[i4];
                acc[4*i4]   += e*vv.x; acc[4*i4+1] += e*vv.y;
                acc[4*i4+2] += e*vv.z; acc[4*i4+3] += e*vv.w;
            }
        }
    }
    size_t pb = ((size_t)(seg*BH + bh)*GG + g);
    float4* pa = (float4*)(pacc + pb*64 + (part << 4));
    #pragma unroll
    for (int i4 = 0; i4 < 4; i4++)
        pa[i4] = make_float4(acc[4*i4], acc[4*i4+1], acc[4*i4+2], acc[4*i4+3]);
    if (part == 0) { pml[pb*2] = mrow; pml[pb*2+1] = lrow; }
}

// combine + scatter (split) fused
__global__ void glob_comb_scat_k(const float* __restrict__ pacc, const float* __restrict__ pml,
                                 const int* __restrict__ idxg,
                                 __half* __restrict__ xhi, __half* __restrict__ xlo) {
    int bh = blockIdx.x, b = bh / HH, h = bh % HH;
    int tid = threadIdx.x;
    int g = tid >> 2, part = tid & 3;
    float ms[NSEG], ls[NSEG];
    float M = -INFINITY;
    #pragma unroll
    for (int s = 0; s < NSEG; s++) {
        size_t pb = ((size_t)(s*BH + bh)*GG + g);
        ms[s] = pml[pb*2]; ls[s] = pml[pb*2+1];
        M = fmaxf(M, ms[s]);
    }
    float L = 0.f;
    float acc[16];
    #pragma unroll
    for (int i = 0; i < 16; i++) acc[i] = 0.f;
    #pragma unroll
    for (int s = 0; s < NSEG; s++) {
        float wgt = __expf(ms[s] - M);
        L += ls[s]*wgt;
        size_t pb = ((size_t)(s*BH + bh)*GG + g);
        const float4* pa = (const float4*)(pacc + pb*64 + (part << 4));
        #pragma unroll
        for (int i4 = 0; i4 < 4; i4++) {
            float4 v = pa[i4];
            acc[4*i4]   += wgt*v.x; acc[4*i4+1] += wgt*v.y;
            acc[4*i4+2] += wgt*v.z; acc[4*i4+3] += wgt*v.w;
        }
    }
    float inv = 1.f / L;
    int dst = idxg[b*GG + g];
    size_t obase = (size_t)(b*SS + dst)*DD + h*DHH + (part << 4);
    #pragma unroll
    for (int i = 0; i < 16; i += 2) {
        float v0 = acc[i]*inv, v1 = acc[i+1]*inv;
        __half h0 = __float2half(v0), h1 = __float2half(v1);
        *(__half2*)&xhi[obase + i] = __halves2half2(h0, h1);
        *(__half2*)&xlo[obase + i] = __halves2half2(
            __float2half(v0 - __half2float(h0)), __float2half(v1 - __half2float(h1)));
    }
}

// ---------------- gather (split) ----------------
__global__ void gather_split_k(const float* __restrict__ x, const int* __restrict__ idxg,
                               __half* __restrict__ xghi, __half* __restrict__ xglo) {
    int r = blockIdx.x;
    int b = r / GG;
    int src = idxg[r];
    for (int d = threadIdx.x; d < DD; d += blockDim.x) {
        float v = x[((size_t)(b*SS+src))*DD + d];
        __half h = __float2half(v);
        xghi[(size_t)r*DD + d] = h;
        xglo[(size_t)r*DD + d] = __float2half(v - __half2float(h));
    }
}

// ---------------- classifier ----------------
__global__ void classify_k(const float* __restrict__ x, const float* __restrict__ Wc,
                           const float* __restrict__ bc, const int* __restrict__ lo_p,
                           const int* __restrict__ ro_p, float* __restrict__ out, int nrows) {
    int r = blockIdx.x;
    int lo = *lo_p, ro = *ro_p;
    int per_b = 63 - lo - ro;
    if (per_b <= 0) per_b = 1;
    int b = r / per_b, t = lo + (r - b*per_b);
    const float* row = x + ((size_t)(b*SS + t))*DD;
    float p[7];
    #pragma unroll
    for (int c = 0; c < 7; c++) p[c] = 0.f;
    for (int d = threadIdx.x; d < DD; d += 256) {
        float xv = row[d];
        #pragma unroll
        for (int c = 0; c < 7; c++) p[c] += xv * Wc[d*7 + c];
    }
    #pragma unroll
    for (int c = 0; c < 7; c++) {
        float tot = blk_sum(p[c]);
        if (threadIdx.x == 0) out[r*7 + c] = tot + bc[c];
    }
}

// ---------------- launch ----------------
extern "C" void kernel_launch(void* const* d_in, const int* in_sizes, int n_in,
                              void* d_out, int out_size) {
    const float* emb_tok = (const float*)d_in[0];
    const float* emb_pos = (const float*)d_in[1];
    const float* ln_e_s  = (const float*)d_in[2];
    const float* ln_e_b  = (const float*)d_in[3];
    const float* Wq  = (const float*)d_in[4];
    const float* bq  = (const float*)d_in[5];
    const float* Wk  = (const float*)d_in[6];
    const float* bk  = (const float*)d_in[7];
    const float* Wv  = (const float*)d_in[8];
    const float* bv  = (const float*)d_in[9];
    const float* Wqg = (const float*)d_in[10];
    const float* bqg = (const float*)d_in[11];
    const float* Wkg = (const float*)d_in[12];
    const float* bkg = (const float*)d_in[13];
    const float* Wvg = (const float*)d_in[14];
    const float* bvg = (const float*)d_in[15];
    const float* Wo  = (const float*)d_in[16];
    const float* bo  = (const float*)d_in[17];
    const float* ln1_s = (const float*)d_in[18];
    const float* ln1_b = (const float*)d_in[19];
    const float* Wf1 = (const float*)d_in[20];
    const float* bf1 = (const float*)d_in[21];
    const float* Wf2 = (const float*)d_in[22];
    const float* bf2 = (const float*)d_in[23];
    const float* ln2_s = (const float*)d_in[24];
    const float* ln2_b = (const float*)d_in[25];
    const float* Wc  = (const float*)d_in[26];
    const float* bc  = (const float*)d_in[27];
    const int* input_ids = (const int*)d_in[28];
    const int* attn_mask = (const int*)d_in[29];
    const int* lo_p = (const int*)d_in[30];
    const int* ro_p = (const int*)d_in[31];
    float* out = (float*)d_out;

    float *x, *qkv, *tmp, *qg, *bcat, *pacc, *pml;
    int* idxg; unsigned char* klo;
    __half *w, *ahi, *alo, *xhi, *xlo, *xghi, *xglo;
    __half *bqh, *bql, *bkh, *bvh, *bvl;
    cudaGetSymbolAddress((void**)&x,    g_x);
    cudaGetSymbolAddress((void**)&qkv,  g_qkv);
    cudaGetSymbolAddress((void**)&tmp,  g_tmp);
    cudaGetSymbolAddress((void**)&qg,   g_qg);
    cudaGetSymbolAddress((void**)&bcat, g_bcat);
    cudaGetSymbolAddress((void**)&pacc, g_pacc);
    cudaGetSymbolAddress((void**)&pml,  g_pml);
    cudaGetSymbolAddress((void**)&idxg, g_idxg);
    cudaGetSymbolAddress((void**)&klo,  g_klo);
    cudaGetSymbolAddress((void**)&w,    g_w);
    cudaGetSymbolAddress((void**)&ahi,  g_ahi);
    cudaGetSymbolAddress((void**)&alo,  g_alo);
    cudaGetSymbolAddress((void**)&xhi,  g_xhi);
    cudaGetSymbolAddress((void**)&xlo,  g_xlo);
    cudaGetSymbolAddress((void**)&xghi, g_xghi);
    cudaGetSymbolAddress((void**)&xglo, g_xglo);
    cudaGetSymbolAddress((void**)&bqh,  g_bqh);
    cudaGetSymbolAddress((void**)&bql,  g_bql);
    cudaGetSymbolAddress((void**)&bkh,  g_bkh);
    cudaGetSymbolAddress((void**)&bvh,  g_bvh);
    cudaGetSymbolAddress((void**)&bvl,  g_bvl);

    cudaFuncSetAttribute(tgemm_k<0>, cudaFuncAttributeMaxDynamicSharedMemorySize, SMEM_GEMM);
    cudaFuncSetAttribute(tgemm_k<1>, cudaFuncAttributeMaxDynamicSharedMemorySize, SMEM_GEMM);
    cudaFuncSetAttribute(tgemm_k<2>, cudaFuncAttributeMaxDynamicSharedMemorySize, SMEM_GEMM);
    cudaFuncSetAttribute(glob_part_k, cudaFuncAttributeMaxDynamicSharedMemorySize, SMEM_GLOB);

    prep_k<<<BB, 256>>>(input_ids, attn_mask, idxg, klo);
    embed_ln_k<<<BS, 256>>>(input_ids, emb_tok, emb_pos, ln_e_s, ln_e_b, x, xhi, xlo);

    // merged weight conversion + bias concat: ONE launch for all 18 matrices + 2 bcats
    wsplit_all_k<<<TILES_ALL, dim3(32, 8)>>>(Wq, Wk, Wv, Wkg, Wvg, Wqg, Wo, Wf1, Wf2,
                                             bq, bk, bv, bkg, bvg, w, bcat);

    dim3 gTqkv(QS/128, BS/128 + 1);
    dim3 gT(DD/128, BS/128);
    dim3 gT1(FFN/128, BS/128);
    dim3 gBandM(SS/128, BH);
    dim3 gGlobP(NSEG, BH);

    for (int l = 0; l < LL; l++) {
        size_t base = (size_t)l * LWOFF;
        const float* bqg_l = bqg + l*DD;
        const float* bo_l  = bo  + l*DD;
        const float* bf1_l = bf1 + l*FFN; const float* bf2_l = bf2 + l*DD;

        gather_split_k<<<BB*GG, 256>>>(x, idxg, xghi, xglo);
        tgemm_k<2><<<gTqkv, 256, SMEM_GEMM>>>(xhi, xlo, w+base+OFF_Q,
                                              bcat + l*QS, qkv, 0, 0, BS, QS, DD,
                                              xghi, xglo, w+base+OFF_QG, bqg_l, qg);

        band_mma_k<<<gBandM, 256>>>(bqh, bql, bkh, bvh, bvl, idxg, klo, xhi, xlo);

        glob_part_k<<<gGlobP, 256, SMEM_GLOB>>>(qg, qkv, attn_mask, pacc, pml);
        glob_comb_scat_k<<<BH, 256>>>(pacc, pml, idxg, xhi, xlo);

        tgemm_k<0><<<gT, 256, SMEM_GEMM>>>(xhi, xlo, w+base+OFF_O,
                                           bo_l, tmp, 0, 0, BS, DD, DD,
                                           0, 0, 0, 0, 0);
        add_ln_k<<<BS, 256>>>(x, tmp, ln1_s + l*DD, ln1_b + l*DD, xhi, xlo);

        tgemm_k<1><<<gT1, 256, SMEM_GEMM>>>(xhi, xlo, w+base+OFF_F1,
                                            bf1_l, 0, ahi, alo, BS, FFN, DD,
                                            0, 0, 0, 0, 0);
        tgemm_k<0><<<gT, 256, SMEM_GEMM>>>(ahi, alo, w+base+OFF_F2,
                                           bf2_l, tmp, 0, 0, BS, DD, FFN,
                                           0, 0, 0, 0, 0);
        add_ln_k<<<BS, 256>>>(x, tmp, ln2_s + l*DD, ln2_b + l*DD, xhi, xlo);
    }

    int nrows = out_size / 7;
    classify_k<<<nrows, 256>>>(x, Wc, bc, lo_p, ro_p, out, nrows);
}

// round 17
// speedup vs baseline: 1.0430x; 1.0003x over previous
#include <cuda_runtime.h>
#include <cuda_fp16.h>
#include <cstdint>
#include <math.h>

#define BB 2
#define SS 4096
#define DD 768
#define HH 12
#define LL 2
#define DHH 64
#define WW 256
#define GG 64
#define FFN 3072
#define SEPID 2
#define NEGV -1000000000.0f
#define BS (BB*SS)
#define QS (5*DD)
#define NSEG 8
#define SEGS (SS/NSEG)
#define BH (BB*HH)

#define WSZ_DD (DD*DD)
#define OFF_Q  0
#define OFF_K  (1*WSZ_DD)
#define OFF_V  (2*WSZ_DD)
#define OFF_KG (3*WSZ_DD)
#define OFF_VG (4*WSZ_DD)
#define OFF_QG (5*WSZ_DD)
#define OFF_O  (6*WSZ_DD)
#define OFF_F1 (7*WSZ_DD)
#define OFF_F2 (7*WSZ_DD + DD*FFN)
#define LWOFF  (7*WSZ_DD + 2*DD*FFN)

// merged weight-conversion tiling
#define NT_DD 576
#define NT_FF 2304
#define TILES_DD (14*NT_DD)
#define TILES_W  (TILES_DD + 4*NT_FF)
#define BCAT_T   (QS/256)
#define TILES_ALL (TILES_W + 2*BCAT_T)

// ---------------- scratch ----------------
__device__ float g_x[BS*DD];
__device__ float g_qkv[(size_t)BS*QS];
__device__ float g_tmp[BS*DD];
__device__ float g_qg[BB*GG*DD];
__device__ float g_bcat[2*QS];
__device__ float g_pacc[NSEG*BH*GG*64];
__device__ float g_pml[NSEG*BH*GG*2];
__device__ int   g_idxg[BB*GG];
__device__ unsigned char g_klo[BS];

__device__ __align__(16) __half g_w[2*LWOFF];
__device__ __align__(16) __half g_ahi[BS*FFN];
__device__ __align__(16) __half g_alo[BS*FFN];
__device__ __align__(16) __half g_xhi[BS*DD];
__device__ __align__(16) __half g_xlo[BS*DD];
__device__ __align__(16) __half g_bqh[BS*DD];
__device__ __align__(16) __half g_bql[BS*DD];
__device__ __align__(16) __half g_bkh[BS*DD];
__device__ __align__(16) __half g_bvh[BS*DD];
__device__ __align__(16) __half g_bvl[BS*DD];

// ---------------- helpers ----------------
__device__ __forceinline__ uint32_t smem_u32(const void* p) {
    uint32_t a;
    asm("{ .reg .u64 t; cvta.to.shared.u64 t, %1; cvt.u32.u64 %0, t; }" : "=r"(a) : "l"(p));
    return a;
}

__device__ __forceinline__ void cp16(uint32_t dst, const void* src) {
    asm volatile("cp.async.ca.shared.global [%0], [%1], 16;" :: "r"(dst), "l"(src));
}
#define CP_COMMIT() asm volatile("cp.async.commit_group;" ::: "memory")
#define CP_WAIT2()  asm volatile("cp.async.wait_group 2;" ::: "memory")

__device__ __forceinline__ void ldmat4(uint32_t& r0, uint32_t& r1, uint32_t& r2, uint32_t& r3,
                                       uint32_t addr) {
    asm volatile("ldmatrix.sync.aligned.m8n8.x4.shared.b16 {%0,%1,%2,%3}, [%4];"
        : "=r"(r0), "=r"(r1), "=r"(r2), "=r"(r3) : "r"(addr));
}

__device__ __forceinline__ void ldmat4t(uint32_t& r0, uint32_t& r1, uint32_t& r2, uint32_t& r3,
                                        uint32_t addr) {
    asm volatile("ldmatrix.sync.aligned.m8n8.x4.trans.shared.b16 {%0,%1,%2,%3}, [%4];"
        : "=r"(r0), "=r"(r1), "=r"(r2), "=r"(r3) : "r"(addr));
}

__device__ __forceinline__ void mma16816(float* d, const uint32_t* a, const uint32_t* b) {
    asm volatile("mma.sync.aligned.m16n8k16.row.col.f32.f16.f16.f32 "
        "{%0,%1,%2,%3}, {%4,%5,%6,%7}, {%8,%9}, {%0,%1,%2,%3};"
        : "+f"(d[0]), "+f"(d[1]), "+f"(d[2]), "+f"(d[3])
        : "r"(a[0]), "r"(a[1]), "r"(a[2]), "r"(a[3]), "r"(b[0]), "r"(b[1]));
}

__device__ __forceinline__ uint32_t packh2(float a, float b) {
    __half2 h = __floats2half2_rn(a, b);
    return *(uint32_t*)&h;
}

__device__ __forceinline__ float gelu_f(float v) {
    return 0.5f*v*(1.f + tanhf(0.7978845608028654f*(v + 0.044715f*v*v*v)));
}

// ---------------- block reductions ----------------
__device__ __forceinline__ float blk_sum(float v) {
    __shared__ float sm[33];
    int lane = threadIdx.x & 31, wid = threadIdx.x >> 5;
    #pragma unroll
    for (int o = 16; o; o >>= 1) v += __shfl_xor_sync(0xffffffffu, v, o);
    if (lane == 0) sm[wid] = v;
    __syncthreads();
    if (wid == 0) {
        int nw = (blockDim.x + 31) >> 5;
        float r = (lane < nw) ? sm[lane] : 0.f;
        #pragma unroll
        for (int o = 16; o; o >>= 1) r += __shfl_xor_sync(0xffffffffu, r, o);
        if (lane == 0) sm[32] = r;
    }
    __syncthreads();
    float r = sm[32];
    __syncthreads();
    return r;
}

// ---------------- prep ----------------
__global__ void prep_k(const int* __restrict__ ids, const int* __restrict__ am,
                       int* __restrict__ idxg, unsigned char* __restrict__ klo) {
    int b = blockIdx.x;
    for (int s = threadIdx.x; s < SS; s += blockDim.x) {
        bool g = (ids[b*SS+s] == SEPID) || (s == 0);
        klo[b*SS+s] = (am[b*SS+s] != 0 && !g) ? 1 : 0;
    }
    if (threadIdx.x == 0) {
        int cnt = 0;
        for (int s = 0; s < SS && cnt < GG; s++)
            if (ids[b*SS+s] == SEPID || s == 0) idxg[b*GG + cnt++] = s;
        for (; cnt < GG; cnt++) idxg[b*GG + cnt] = 0;
    }
}

// ---------------- embedding + LN ----------------
__global__ void embed_ln_k(const int* __restrict__ ids, const float* __restrict__ etok,
                           const float* __restrict__ epos, const float* __restrict__ lns,
                           const float* __restrict__ lnb, float* __restrict__ x,
                           __half* __restrict__ xhi, __half* __restrict__ xlo) {
    int row = blockIdx.x;
    int spos = row & (SS - 1);
    int id = ids[row];
    const float* te = etok + (size_t)id * DD;
    const float* pe = epos + (size_t)spos * DD;
    float v[3]; float sum = 0.f;
    #pragma unroll
    for (int i = 0; i < 3; i++) {
        int d = threadIdx.x + i*256;
        float val = te[d] + pe[d];
        v[i] = val; sum += val;
    }
    float mean = blk_sum(sum) * (1.0f/DD);
    float sq = 0.f;
    #pragma unroll
    for (int i = 0; i < 3; i++) { float c = v[i] - mean; sq += c*c; }
    float inv = rsqrtf(blk_sum(sq) * (1.0f/DD) + 1e-5f);
    #pragma unroll
    for (int i = 0; i < 3; i++) {
        int d = threadIdx.x + i*256;
        float o = (v[i] - mean)*inv*lns[d] + lnb[d];
        x[(size_t)row*DD + d] = o;
        __half h = __float2half(o);
        xhi[(size_t)row*DD + d] = h;
        xlo[(size_t)row*DD + d] = __float2half(o - __half2float(h));
    }
}

// ---------------- residual add + LN ----------------
__global__ void add_ln_k(float* __restrict__ x, const float* __restrict__ t,
                         const float* __restrict__ lns, const float* __restrict__ lnb,
                         __half* __restrict__ xhi, __half* __restrict__ xlo) {
    int row = blockIdx.x;
    size_t base = (size_t)row * DD;
    float v[3]; float sum = 0.f;
    #pragma unroll
    for (int i = 0; i < 3; i++) {
        int d = threadIdx.x + i*256;
        float val = x[base+d] + t[base+d];
        v[i] = val; sum += val;
    }
    float mean = blk_sum(sum) * (1.0f/DD);
    float sq = 0.f;
    #pragma unroll
    for (int i = 0; i < 3; i++) { float c = v[i] - mean; sq += c*c; }
    float inv = rsqrtf(blk_sum(sq) * (1.0f/DD) + 1e-5f);
    #pragma unroll
    for (int i = 0; i < 3; i++) {
        int d = threadIdx.x + i*256;
        float o = (v[i] - mean)*inv*lns[d] + lnb[d];
        x[base+d] = o;
        __half h = __float2half(o);
        xhi[base+d] = h;
        xlo[base+d] = __float2half(o - __half2float(h));
    }
}

// ---------------- merged weight conversion + bias concat (one launch) -----------
__global__ void wsplit_all_k(
        const float* __restrict__ Wq,  const float* __restrict__ Wk,
        const float* __restrict__ Wv,  const float* __restrict__ Wkg,
        const float* __restrict__ Wvg, const float* __restrict__ Wqg,
        const float* __restrict__ Wo,  const float* __restrict__ Wf1,
        const float* __restrict__ Wf2,
        const float* __restrict__ bq,  const float* __restrict__ bk,
        const float* __restrict__ bv,  const float* __restrict__ bkg,
        const float* __restrict__ bvg,
        __half* __restrict__ w, float* __restrict__ bcat) {
    int tile = blockIdx.x;
    int tx = threadIdx.x, ty = threadIdx.y;
    if (tile >= TILES_W) {
        int t2 = tile - TILES_W;
        int l = t2 / BCAT_T, blk = t2 - l*BCAT_T;
        int i = blk*256 + ty*32 + tx;
        int seg = i / DD, off = i - seg*DD;
        const float* src = (seg == 0) ? bq : (seg == 1) ? bk : (seg == 2) ? bv
                         : (seg == 3) ? bkg : bvg;
        bcat[l*QS + i] = src[l*DD + off];
        return;
    }
    __shared__ float t[32][33];
    const float* src; size_t doff; int K, N, lt;
    if (tile < TILES_DD) {
        int mi = tile / NT_DD; lt = tile - mi*NT_DD;
        int l = mi / 7, m = mi - l*7;
        size_t base = (size_t)l * LWOFF;
        K = DD; N = DD;
        switch (m) {
            case 0: src = Wq  + (size_t)l*DD*DD; doff = base + OFF_Q;  break;
            case 1: src = Wk  + (size_t)l*DD*DD; doff = base + OFF_K;  break;
            case 2: src = Wv  + (size_t)l*DD*DD; doff = base + OFF_V;  break;
            case 3: src = Wkg + (size_t)l*DD*DD; doff = base + OFF_KG; break;
            case 4: src = Wvg + (size_t)l*DD*DD; doff = base + OFF_VG; break;
            case 5: src = Wqg + (size_t)l*DD*DD; doff = base + OFF_QG; break;
            default: src = Wo + (size_t)l*DD*DD; doff = base + OFF_O;  break;
        }
    } else {
        int t2 = tile - TILES_DD;
        int q = t2 / NT_FF; lt = t2 - q*NT_FF;
        int l = q >> 1; int isF2 = q & 1;
        size_t base = (size_t)l * LWOFF;
        if (!isF2) { src = Wf1 + (size_t)l*DD*FFN; doff = base + OFF_F1; K = DD; N = FFN; }
        else       { src = Wf2 + (size_t)l*FFN*DD; doff = base + OFF_F2; K = FFN; N = DD; }
    }
    int ntx = N >> 5;
    int n0 = (lt % ntx) << 5, k0 = (lt / ntx) << 5;
    #pragma unroll
    for (int i = 0; i < 4; i++)
        t[ty+8*i][tx] = src[(size_t)(k0+ty+8*i)*N + n0 + tx];
    __syncthreads();
    __half* hi = w + doff;
    #pragma unroll
    for (int i = 0; i < 4; i++)
        hi[(size_t)(n0+ty+8*i)*K + k0 + tx] = __float2half(t[tx][ty+8*i]);
}

// ---------------- tensor-core GEMM: BK=32, cp.async 4-stage, fp16 2-pass --------
// MODE 0: C fp32.  MODE 1: gelu -> Chi/Clo fp16.
// MODE 2: QKV split epilogue; extra by-row computes QG GEMM with A-row
//         indirection through idxg (reads xhi/xlo directly, no gather kernel).
#define SPAD 40
#define STG_BYTES (128*SPAD*2)
#define SMEM_GEMM (8*STG_BYTES)

template<int MODE>
__global__ void __launch_bounds__(256, 2) tgemm_k(
        const __half* __restrict__ Ahi, const __half* __restrict__ Alo,
        const __half* __restrict__ B_,
        const float* __restrict__ bias_, float* __restrict__ C,
        __half* __restrict__ Chi, __half* __restrict__ Clo,
        int M, int N_, int K,
        const __half* B2, const float* bias2, float* C2,
        const int* __restrict__ idxg) {
    extern __shared__ char smem[];
    const uint32_t sm0 = smem_u32(smem);
    const bool qgp = (MODE == 2) && ((int)blockIdx.y == (BS >> 7));
    if (qgp && blockIdx.x >= DD/128) return;
    const __half* B   = qgp ? B2   : B_;
    const float* bias = qgp ? bias2 : bias_;
    const int N = qgp ? DD : N_;
    const int bn = blockIdx.x << 7;
    const int bm = qgp ? 0 : (blockIdx.y << 7);
    const int tid = threadIdx.x, wid = tid >> 5, lane = tid & 31;
    const int wm = (wid >> 2) << 6;
    const int wn = (wid & 3) << 5;

    float acc[4][4][4];
    #pragma unroll
    for (int i = 0; i < 4; i++)
        #pragma unroll
        for (int j = 0; j < 4; j++)
            #pragma unroll
            for (int r = 0; r < 4; r++) acc[i][j][r] = 0.f;

    const int KC = K >> 5;
    const int total = 2 * KC;
    const __half* Aps[2] = {Ahi, Alo};

    const int r0 = tid >> 2, c0 = (tid & 3) << 3;
    const int r1 = r0 + 64;
    // A-row indices (with idxg indirection on the QG path)
    int ga0 = bm + r0, ga1 = bm + r1;
    if (qgp) {
        ga0 = idxg[r0];            // r0 in [0,64) -> batch 0
        ga1 = SS + idxg[r1];       // r1 in [64,128) -> batch 1 (idxg[64+g])
    }
    const uint32_t dA0 = (uint32_t)((r0*SPAD + c0) << 1);
    const uint32_t dA1 = (uint32_t)((r1*SPAD + c0) << 1);

    const int lrow = lane & 15, lcol = (lane >> 4) << 3;
    const uint32_t offA = (uint32_t)(((wm + lrow) * SPAD + lcol) << 1);
    const uint32_t offB = (uint32_t)(((wn + lrow) * SPAD + lcol) << 1) + 4*STG_BYTES;

    #pragma unroll
    for (int p = 0; p < 3; p++) {
        const int pass = (p < KC) ? 0 : 1;
        const int kc = p - pass*KC;
        const __half* Ap = Aps[pass];
        const int kb = kc << 5;
        const uint32_t sa = sm0 + p*STG_BYTES;
        const uint32_t sb = sm0 + 4*STG_BYTES + p*STG_BYTES;
        cp16(sa + dA0, Ap + (size_t)ga0*K + kb + c0);
        cp16(sa + dA1, Ap + (size_t)ga1*K + kb + c0);
        cp16(sb + dA0, B + (size_t)(bn + r0)*K + kb + c0);
        cp16(sb + dA1, B + (size_t)(bn + r1)*K + kb + c0);
        CP_COMMIT();
    }

    for (int s = 0; s < total; s++) {
        CP_WAIT2();
        __syncthreads();
        const int p = s + 3;
        if (p < total) {
            const int pass = (p < KC) ? 0 : 1;
            const int kc = p - pass*KC;
            const __half* Ap = Aps[pass];
            const int kb = kc << 5;
            const int st2 = p & 3;
            const uint32_t sa = sm0 + st2*STG_BYTES;
            const uint32_t sb = sm0 + 4*STG_BYTES + st2*STG_BYTES;
            cp16(sa + dA0, Ap + (size_t)ga0*K + kb + c0);
            cp16(sa + dA1, Ap + (size_t)ga1*K + kb + c0);
            cp16(sb + dA0, B + (size_t)(bn + r0)*K + kb + c0);
            cp16(sb + dA1, B + (size_t)(bn + r1)*K + kb + c0);
        }
        CP_COMMIT();
        const int stg = s & 3;
        const uint32_t abase = sm0 + stg*STG_BYTES + offA;
        const uint32_t bbase = sm0 + stg*STG_BYTES + offB;
        #pragma unroll
        for (int ks = 0; ks < 2; ks++) {
            uint32_t af[4][4], bf[4][2];
            #pragma unroll
            for (int mt = 0; mt < 4; mt++)
                ldmat4(af[mt][0], af[mt][1], af[mt][2], af[mt][3],
                       abase + (uint32_t)(((mt << 4) * SPAD + (ks << 4)) << 1));
            #pragma unroll
            for (int np = 0; np < 2; np++) {
                uint32_t m0, m1, m2, m3;
                ldmat4(m0, m1, m2, m3,
                       bbase + (uint32_t)(((np << 4) * SPAD + (ks << 4)) << 1));
                bf[2*np][0] = m0; bf[2*np+1][0] = m1;
                bf[2*np][1] = m2; bf[2*np+1][1] = m3;
            }
            #pragma unroll
            for (int mt = 0; mt < 4; mt++)
                #pragma unroll
                for (int nt = 0; nt < 4; nt++)
                    mma16816(acc[mt][nt], af[mt], bf[nt]);
        }
    }

    const int mrow = lane >> 2, ncol = (lane & 3) << 1;
    const int seg = bn / DD;
    #pragma unroll
    for (int mt = 0; mt < 4; mt++) {
        #pragma unroll
        for (int nt = 0; nt < 4; nt++) {
            int r = bm + wm + (mt << 4) + mrow;
            int c = bn + wn + (nt << 3) + ncol;
            float b0 = bias[c], b1 = bias[c+1];
            float v0 = acc[mt][nt][0] + b0, v1 = acc[mt][nt][1] + b1;
            float v2 = acc[mt][nt][2] + b0, v3 = acc[mt][nt][3] + b1;
            if (MODE == 1) {
                v0 = gelu_f(v0); v1 = gelu_f(v1); v2 = gelu_f(v2); v3 = gelu_f(v3);
                __half h0 = __float2half(v0), h1 = __float2half(v1);
                __half h2 = __float2half(v2), h3 = __float2half(v3);
                *(__half2*)&Chi[(size_t)r*N + c]     = __halves2half2(h0, h1);
                *(__half2*)&Chi[(size_t)(r+8)*N + c] = __halves2half2(h2, h3);
                *(__half2*)&Clo[(size_t)r*N + c]     = __halves2half2(
                    __float2half(v0 - __half2float(h0)), __float2half(v1 - __half2float(h1)));
                *(__half2*)&Clo[(size_t)(r+8)*N + c] = __halves2half2(
                    __float2half(v2 - __half2float(h2)), __float2half(v3 - __half2float(h3)));
            } else if (MODE == 2) {
                if (qgp) {
                    *(float2*)&C2[(size_t)r*DD + c]     = make_float2(v0, v1);
                    *(float2*)&C2[(size_t)(r+8)*DD + c] = make_float2(v2, v3);
                } else if (seg <= 2) {
                    int cc = c - seg*DD;
                    size_t o0 = (size_t)r*DD + cc, o1 = (size_t)(r+8)*DD + cc;
                    __half h0 = __float2half(v0), h1 = __float2half(v1);
                    __half h2 = __float2half(v2), h3 = __float2half(v3);
                    __half2 hi0 = __halves2half2(h0, h1), hi1 = __halves2half2(h2, h3);
                    __half2 lo0 = __halves2half2(__float2half(v0 - __half2float(h0)),
                                                 __float2half(v1 - __half2float(h1)));
                    __half2 lo1 = __halves2half2(__float2half(v2 - __half2float(h2)),
                                                 __float2half(v3 - __half2float(h3)));
                    if (seg == 0) {
                        *(__half2*)&g_bqh[o0] = hi0; *(__half2*)&g_bqh[o1] = hi1;
                        *(__half2*)&g_bql[o0] = lo0; *(__half2*)&g_bql[o1] = lo1;
                    } else if (seg == 1) {
                        *(__half2*)&g_bkh[o0] = hi0; *(__half2*)&g_bkh[o1] = hi1;
                    } else {
                        *(__half2*)&g_bvh[o0] = hi0; *(__half2*)&g_bvh[o1] = hi1;
                        *(__half2*)&g_bvl[o0] = lo0; *(__half2*)&g_bvl[o1] = lo1;
                    }
                } else {
                    *(float2*)&C[(size_t)r*N + c]     = make_float2(v0, v1);
                    *(float2*)&C[(size_t)(r+8)*N + c] = make_float2(v2, v3);
                }
            } else {
                *(float2*)&C[(size_t)r*N + c]     = make_float2(v0, v1);
                *(float2*)&C[(size_t)(r+8)*N + c] = make_float2(v2, v3);
            }
        }
    }
}

// ---------------- band attention via mma (static smem, occ 2) ----------------
#define QP 72
#define KP 72

__global__ void __launch_bounds__(256) band_mma_k(
        const __half* __restrict__ bqh, const __half* __restrict__ bql,
        const __half* __restrict__ bkh,
        const __half* __restrict__ bvh, const __half* __restrict__ bvl,
        const int* __restrict__ idxg, const unsigned char* __restrict__ klo,
        __half* __restrict__ ohi, __half* __restrict__ olo) {
    __shared__ __half smh[2*128*QP];
    unsigned char* klos = (unsigned char*)(smh + 3*64*KP);
    const uint32_t smb = smem_u32(smh);
    const int qt = blockIdx.x, bh = blockIdx.y;
    const int b = bh / HH, h = bh % HH;
    const int n = qt >> 1, r0 = (qt & 1) << 7;
    const int tid = threadIdx.x, w = tid >> 5, lane = tid & 31;
    const int t0 = n*WW + r0;
    const int lrow = lane & 15, lcol = (lane >> 4) << 3;

    #pragma unroll
    for (int t = 0; t < 4; t++) {
        int u = tid + (t << 8);
        int row = u >> 3, c8 = (u & 7) << 3;
        size_t src = (size_t)(b*SS + t0 + row)*DD + h*DHH + c8;
        *(uint4*)&smh[row*QP + c8]          = *(const uint4*)&bqh[src];
        *(uint4*)&smh[128*QP + row*QP + c8] = *(const uint4*)&bql[src];
    }
    __syncthreads();
    uint32_t afh[4][4], afl[4][4];
    #pragma unroll
    for (int ks = 0; ks < 4; ks++) {
        uint32_t a0 = smb + (uint32_t)(((w*16 + lrow)*QP + ks*16 + lcol) << 1);
        ldmat4(afh[ks][0], afh[ks][1], afh[ks][2], afh[ks][3], a0);
        ldmat4(afl[ks][0], afl[ks][1], afl[ks][2], afl[ks][3], a0 + (uint32_t)(128*QP*2));
    }

    float acco[8][4];
    #pragma unroll
    for (int nt = 0; nt < 8; nt++)
        #pragma unroll
        for (int r = 0; r < 4; r++) acco[nt][r] = 0.f;
    float m0 = -INFINITY, m1 = -INFINITY, l0 = 0.f, l1 = 0.f;
    const int qw0 = r0 + w*16 + (lane >> 2);
    const int cstart = (qt & 1) << 1;

    for (int cc = 0; cc <= 10; cc++) {
        const int c = (cc < 10) ? (cstart + cc) : 12;
        const int kpb = n*WW + (c << 6) - WW;
        __syncthreads();
        #pragma unroll
        for (int t = 0; t < 2; t++) {
            int u = tid + (t << 8);
            int row = u >> 3, c8 = (u & 7) << 3;
            int gk; bool valid;
            if (c == 12) { gk = idxg[b*GG + row]; valid = true; }
            else { gk = kpb + row; valid = (gk >= 0) && (gk < SS); }
            uint4 z = make_uint4(0,0,0,0);
            size_t src = (size_t)(b*SS + gk)*DD + h*DHH + c8;
            *(uint4*)&smh[row*KP + c8]          = valid ? *(const uint4*)&bkh[src] : z;
            *(uint4*)&smh[64*KP + row*KP + c8]  = valid ? *(const uint4*)&bvh[src] : z;
            *(uint4*)&smh[128*KP + row*KP + c8] = valid ? *(const uint4*)&bvl[src] : z;
            if (c8 == 0) klos[row] = (c != 12 && valid) ? klo[b*SS + gk] : 0;
        }
        __syncthreads();

        float accs[8][4];
        #pragma unroll
        for (int nt = 0; nt < 8; nt++)
            #pragma unroll
            for (int r = 0; r < 4; r++) accs[nt][r] = 0.f;
        #pragma unroll
        for (int ks = 0; ks < 4; ks++) {
            uint32_t bf[8][2];
            #pragma unroll
            for (int np = 0; np < 4; np++) {
                uint32_t q0, q1, q2, q3;
                ldmat4(q0, q1, q2, q3,
                       smb + (uint32_t)(((np*16 + lrow)*KP + ks*16 + lcol) << 1));
                bf[2*np][0] = q0; bf[2*np+1][0] = q1;
                bf[2*np][1] = q2; bf[2*np+1][1] = q3;
            }
            #pragma unroll
            for (int nt = 0; nt < 8; nt++) mma16816(accs[nt], afh[ks], bf[nt]);
            #pragma unroll
            for (int nt = 0; nt < 8; nt++) mma16816(accs[nt], afl[ks], bf[nt]);
        }
        float cm0 = -3.4e38f, cm1 = -3.4e38f;
        #pragma unroll
        for (int nt = 0; nt < 8; nt++) {
            int col0 = nt*8 + ((lane & 3) << 1);
            #pragma unroll
            for (int e = 0; e < 2; e++) {
                int col = col0 + e;
                float s0 = accs[nt][e]   * 0.125f;
                float s1 = accs[nt][2+e] * 0.125f;
                if (c != 12) {
                    int gk = kpb + col;
                    bool okc = (gk >= 0) && (gk < SS) && klos[col];
                    int j = (c << 6) + col;
                    if (!(okc && j >= qw0     && j <= qw0 + 512))     s0 = NEGV;
                    if (!(okc && j >= qw0 + 8 && j <= qw0 + 8 + 512)) s1 = NEGV;
                }
                accs[nt][e] = s0; accs[nt][2+e] = s1;
                cm0 = fmaxf(cm0, s0); cm1 = fmaxf(cm1, s1);
            }
        }
        cm0 = fmaxf(cm0, __shfl_xor_sync(0xffffffffu, cm0, 1));
        cm0 = fmaxf(cm0, __shfl_xor_sync(0xffffffffu, cm0, 2));
        cm1 = fmaxf(cm1, __shfl_xor_sync(0xffffffffu, cm1, 1));
        cm1 = fmaxf(cm1, __shfl_xor_sync(0xffffffffu, cm1, 2));
        float mn0 = fmaxf(m0, cm0), mn1 = fmaxf(m1, cm1);
        float rs0 = __expf(m0 - mn0), rs1 = __expf(m1 - mn1);
        uint32_t pfu[4][4];
        float ls0 = 0.f, ls1 = 0.f;
        #pragma unroll
        for (int t = 0; t < 4; t++) {
            int nA = 2*t, nB = 2*t + 1;
            float e00 = __expf(accs[nA][0] - mn0), e01 = __expf(accs[nA][1] - mn0);
            float e10 = __expf(accs[nA][2] - mn1), e11 = __expf(accs[nA][3] - mn1);
            float f00 = __expf(accs[nB][0] - mn0), f01 = __expf(accs[nB][1] - mn0);
            float f10 = __expf(accs[nB][2] - mn1), f11 = __expf(accs[nB][3] - mn1);
            ls0 += e00 + e01 + f00 + f01;
            ls1 += e10 + e11 + f10 + f11;
            pfu[t][0] = packh2(e00, e01);
            pfu[t][1] = packh2(e10, e11);
            pfu[t][2] = packh2(f00, f01);
            pfu[t][3] = packh2(f10, f11);
        }
        ls0 += __shfl_xor_sync(0xffffffffu, ls0, 1);
        ls0 += __shfl_xor_sync(0xffffffffu, ls0, 2);
        ls1 += __shfl_xor_sync(0xffffffffu, ls1, 1);
        ls1 += __shfl_xor_sync(0xffffffffu, ls1, 2);
        l0 = l0*rs0 + ls0; l1 = l1*rs1 + ls1;
        m0 = mn0; m1 = mn1;
        #pragma unroll
        for (int nt = 0; nt < 8; nt++) {
            acco[nt][0] *= rs0; acco[nt][1] *= rs0;
            acco[nt][2] *= rs1; acco[nt][3] *= rs1;
        }
        #pragma unroll
        for (int ks = 0; ks < 4; ks++) {
            uint32_t bv[8][2], bw[8][2];
            #pragma unroll
            for (int dt = 0; dt < 4; dt++) {
                uint32_t q0, q1, q2, q3;
                uint32_t ad = smb + (uint32_t)((64*KP + (ks*16 + lrow)*KP + dt*16 + lcol) << 1);
                ldmat4t(q0, q1, q2, q3, ad);
                bv[2*dt][0] = q0; bv[2*dt][1] = q1;
                bv[2*dt+1][0] = q2; bv[2*dt+1][1] = q3;
                ldmat4t(q0, q1, q2, q3, ad + (uint32_t)(64*KP*2));
                bw[2*dt][0] = q0; bw[2*dt][1] = q1;
                bw[2*dt+1][0] = q2; bw[2*dt+1][1] = q3;
            }
            #pragma unroll
            for (int nt = 0; nt < 8; nt++) mma16816(acco[nt], pfu[ks], bv[nt]);
            #pragma unroll
            for (int nt = 0; nt < 8; nt++) mma16816(acco[nt], pfu[ks], bw[nt]);
        }
    }
    float i0 = 1.f / l0, i1 = 1.f / l1;
    int grow = b*SS + t0 + w*16 + (lane >> 2);
    #pragma unroll
    for (int nt = 0; nt < 8; nt++) {
        int col = h*DHH + nt*8 + ((lane & 3) << 1);
        float v0 = acco[nt][0]*i0, v1 = acco[nt][1]*i0;
        float v2 = acco[nt][2]*i1, v3 = acco[nt][3]*i1;
        __half h0 = __float2half(v0), h1 = __float2half(v1);
        __half h2 = __float2half(v2), h3 = __float2half(v3);
        *(__half2*)&ohi[(size_t)grow*DD + col]     = __halves2half2(h0, h1);
        *(__half2*)&ohi[(size_t)(grow+8)*DD + col] = __halves2half2(h2, h3);
        *(__half2*)&olo[(size_t)grow*DD + col]     = __halves2half2(
            __float2half(v0 - __half2float(h0)), __float2half(v1 - __half2float(h1)));
        *(__half2*)&olo[(size_t)(grow+8)*DD + col] = __halves2half2(
            __float2half(v2 - __half2float(h2)), __float2half(v3 - __half2float(h3)));
    }
}

// ---------------- global attention: segmented partials ----------------
#define KSP 68
#define SMEM_GLOB ((2*128*KSP + 64*132) * 4)

__global__ void __launch_bounds__(256, 1) glob_part_k(
        const float* __restrict__ qg, const float* __restrict__ qkv,
        const int* __restrict__ am, float* __restrict__ pacc, float* __restrict__ pml) {
    extern __shared__ float sm[];
    float* Ks = sm;
    float* Vs = sm + 128*KSP;
    float* ps = sm + 2*128*KSP;
    int seg = blockIdx.x;
    int bh = blockIdx.y, b = bh / HH, h = bh % HH;
    int tid = threadIdx.x;
    int g = tid >> 2, part = tid & 3;

    float qv[64];
    const float4* qp = (const float4*)(qg + (size_t)(b*GG+g)*DD + h*DHH);
    #pragma unroll
    for (int d4 = 0; d4 < 16; d4++) {
        float4 t = qp[d4];
        qv[4*d4] = t.x; qv[4*d4+1] = t.y; qv[4*d4+2] = t.z; qv[4*d4+3] = t.w;
    }
    float acc[16];
    #pragma unroll
    for (int i = 0; i < 16; i++) acc[i] = 0.f;
    float mrow = -INFINITY, lrow = 0.f;

    for (int c = 0; c < SEGS/128; c++) {
        int s0 = seg*SEGS + c*128;
        __syncthreads();
        #pragma unroll
        for (int t = 0; t < 8; t++) {
            int idx = tid + (t << 8);
            int row = idx >> 4, c4 = idx & 15;
            const float* src = qkv + (size_t)(b*SS + s0 + row)*QS + h*DHH + (c4 << 2);
            *(float4*)&Ks[row*KSP + (c4 << 2)] = *(const float4*)(src + 3*DD);
            *(float4*)&Vs[row*KSP + (c4 << 2)] = *(const float4*)(src + 4*DD);
        }
        __syncthreads();
        float es[32];
        float cmax = -INFINITY;
        #pragma unroll 4
        for (int i = 0; i < 32; i++) {
            int kk = (i << 2) + part;
            const float4* kr = (const float4*)(Ks + kk*KSP);
            float dot = 0.f;
            #pragma unroll
            for (int d4 = 0; d4 < 16; d4++) {
                float4 kv = kr[d4];
                dot += qv[4*d4]*kv.x + qv[4*d4+1]*kv.y + qv[4*d4+2]*kv.z + qv[4*d4+3]*kv.w;
            }
            float val = (am[b*SS + s0 + kk] != 0) ? dot*0.125f : NEGV;
            es[i] = val; cmax = fmaxf(cmax, val);
        }
        cmax = fmaxf(cmax, __shfl_xor_sync(0xffffffffu, cmax, 1));
        cmax = fmaxf(cmax, __shfl_xor_sync(0xffffffffu, cmax, 2));
        float mnew = fmaxf(mrow, cmax);
        float rs = __expf(mrow - mnew);
        float lsum = 0.f;
        #pragma unroll 4
        for (int i = 0; i < 32; i++) {
            float e = __expf(es[i] - mnew);
            ps[g*132 + (i << 2) + part] = e;
            lsum += e;
        }
        lsum += __shfl_xor_sync(0xffffffffu, lsum, 1);
        lsum += __shfl_xor_sync(0xffffffffu, lsum, 2);
        lrow = lrow*rs + lsum;
        #pragma unroll
        for (int i = 0; i < 16; i++) acc[i] *= rs;
        mrow = mnew;
        __syncthreads();
        for (int kk = 0; kk < 128; kk++) {
            float e = ps[g*132 + kk];
            const float4* vr = (const float4*)(Vs + kk*KSP + (part << 4));
            #pragma unroll
            for (int i4 = 0; i4 < 4; i4++) {
                float4 vv = vr[i4];
                acc[4*i4]   += e*vv.x; acc[4*i4+1] += e*vv.y;
                acc[4*i4+2] += e*vv.z; acc[4*i4+3] += e*vv.w;
            }
        }
    }
    size_t pb = ((size_t)(seg*BH + bh)*GG + g);
    float4* pa = (float4*)(pacc + pb*64 + (part << 4));
    #pragma unroll
    for (int i4 = 0; i4 < 4; i4++)
        pa[i4] = make_float4(acc[4*i4], acc[4*i4+1], acc[4*i4+2], acc[4*i4+3]);
    if (part == 0) { pml[pb*2] = mrow; pml[pb*2+1] = lrow; }
}

// combine + scatter (split) fused
__global__ void glob_comb_scat_k(const float* __restrict__ pacc, const float* __restrict__ pml,
                                 const int* __restrict__ idxg,
                                 __half* __restrict__ xhi, __half* __restrict__ xlo) {
    int bh = blockIdx.x, b = bh / HH, h = bh % HH;
    int tid = threadIdx.x;
    int g = tid >> 2, part = tid & 3;
    float ms[NSEG], ls[NSEG];
    float M = -INFINITY;
    #pragma unroll
    for (int s = 0; s < NSEG; s++) {
        size_t pb = ((size_t)(s*BH + bh)*GG + g);
        ms[s] = pml[pb*2]; ls[s] = pml[pb*2+1];
        M = fmaxf(M, ms[s]);
    }
    float L = 0.f;
    float acc[16];
    #pragma unroll
    for (int i = 0; i < 16; i++) acc[i] = 0.f;
    #pragma unroll
    for (int s = 0; s < NSEG; s++) {
        float wgt = __expf(ms[s] - M);
        L += ls[s]*wgt;
        size_t pb = ((size_t)(s*BH + bh)*GG + g);
        const float4* pa = (const float4*)(pacc + pb*64 + (part << 4));
        #pragma unroll
        for (int i4 = 0; i4 < 4; i4++) {
            float4 v = pa[i4];
            acc[4*i4]   += wgt*v.x; acc[4*i4+1] += wgt*v.y;
            acc[4*i4+2] += wgt*v.z; acc[4*i4+3] += wgt*v.w;
        }
    }
    float inv = 1.f / L;
    int dst = idxg[b*GG + g];
    size_t obase = (size_t)(b*SS + dst)*DD + h*DHH + (part << 4);
    #pragma unroll
    for (int i = 0; i < 16; i += 2) {
        float v0 = acc[i]*inv, v1 = acc[i+1]*inv;
        __half h0 = __float2half(v0), h1 = __float2half(v1);
        *(__half2*)&xhi[obase + i] = __halves2half2(h0, h1);
        *(__half2*)&xlo[obase + i] = __halves2half2(
            __float2half(v0 - __half2float(h0)), __float2half(v1 - __half2float(h1)));
    }
}

// ---------------- classifier ----------------
__global__ void classify_k(const float* __restrict__ x, const float* __restrict__ Wc,
                           const float* __restrict__ bc, const int* __restrict__ lo_p,
                           const int* __restrict__ ro_p, float* __restrict__ out, int nrows) {
    int r = blockIdx.x;
    int lo = *lo_p, ro = *ro_p;
    int per_b = 63 - lo - ro;
    if (per_b <= 0) per_b = 1;
    int b = r / per_b, t = lo + (r - b*per_b);
    const float* row = x + ((size_t)(b*SS + t))*DD;
    float p[7];
    #pragma unroll
    for (int c = 0; c < 7; c++) p[c] = 0.f;
    for (int d = threadIdx.x; d < DD; d += 256) {
        float xv = row[d];
        #pragma unroll
        for (int c = 0; c < 7; c++) p[c] += xv * Wc[d*7 + c];
    }
    #pragma unroll
    for (int c = 0; c < 7; c++) {
        float tot = blk_sum(p[c]);
        if (threadIdx.x == 0) out[r*7 + c] = tot + bc[c];
    }
}

// ---------------- launch ----------------
extern "C" void kernel_launch(void* const* d_in, const int* in_sizes, int n_in,
                              void* d_out, int out_size) {
    const float* emb_tok = (const float*)d_in[0];
    const float* emb_pos = (const float*)d_in[1];
    const float* ln_e_s  = (const float*)d_in[2];
    const float* ln_e_b  = (const float*)d_in[3];
    const float* Wq  = (const float*)d_in[4];
    const float* bq  = (const float*)d_in[5];
    const float* Wk  = (const float*)d_in[6];
    const float* bk  = (const float*)d_in[7];
    const float* Wv  = (const float*)d_in[8];
    const float* bv  = (const float*)d_in[9];
    const float* Wqg = (const float*)d_in[10];
    const float* bqg = (const float*)d_in[11];
    const float* Wkg = (const float*)d_in[12];
    const float* bkg = (const float*)d_in[13];
    const float* Wvg = (const float*)d_in[14];
    const float* bvg = (const float*)d_in[15];
    const float* Wo  = (const float*)d_in[16];
    const float* bo  = (const float*)d_in[17];
    const float* ln1_s = (const float*)d_in[18];
    const float* ln1_b = (const float*)d_in[19];
    const float* Wf1 = (const float*)d_in[20];
    const float* bf1 = (const float*)d_in[21];
    const float* Wf2 = (const float*)d_in[22];
    const float* bf2 = (const float*)d_in[23];
    const float* ln2_s = (const float*)d_in[24];
    const float* ln2_b = (const float*)d_in[25];
    const float* Wc  = (const float*)d_in[26];
    const float* bc  = (const float*)d_in[27];
    const int* input_ids = (const int*)d_in[28];
    const int* attn_mask = (const int*)d_in[29];
    const int* lo_p = (const int*)d_in[30];
    const int* ro_p = (const int*)d_in[31];
    float* out = (float*)d_out;

    float *x, *qkv, *tmp, *qg, *bcat, *pacc, *pml;
    int* idxg; unsigned char* klo;
    __half *w, *ahi, *alo, *xhi, *xlo;
    __half *bqh, *bql, *bkh, *bvh, *bvl;
    cudaGetSymbolAddress((void**)&x,    g_x);
    cudaGetSymbolAddress((void**)&qkv,  g_qkv);
    cudaGetSymbolAddress((void**)&tmp,  g_tmp);
    cudaGetSymbolAddress((void**)&qg,   g_qg);
    cudaGetSymbolAddress((void**)&bcat, g_bcat);
    cudaGetSymbolAddress((void**)&pacc, g_pacc);
    cudaGetSymbolAddress((void**)&pml,  g_pml);
    cudaGetSymbolAddress((void**)&idxg, g_idxg);
    cudaGetSymbolAddress((void**)&klo,  g_klo);
    cudaGetSymbolAddress((void**)&w,    g_w);
    cudaGetSymbolAddress((void**)&ahi,  g_ahi);
    cudaGetSymbolAddress((void**)&alo,  g_alo);
    cudaGetSymbolAddress((void**)&xhi,  g_xhi);
    cudaGetSymbolAddress((void**)&xlo,  g_xlo);
    cudaGetSymbolAddress((void**)&bqh,  g_bqh);
    cudaGetSymbolAddress((void**)&bql,  g_bql);
    cudaGetSymbolAddress((void**)&bkh,  g_bkh);
    cudaGetSymbolAddress((void**)&bvh,  g_bvh);
    cudaGetSymbolAddress((void**)&bvl,  g_bvl);

    cudaFuncSetAttribute(tgemm_k<0>, cudaFuncAttributeMaxDynamicSharedMemorySize, SMEM_GEMM);
    cudaFuncSetAttribute(tgemm_k<1>, cudaFuncAttributeMaxDynamicSharedMemorySize, SMEM_GEMM);
    cudaFuncSetAttribute(tgemm_k<2>, cudaFuncAttributeMaxDynamicSharedMemorySize, SMEM_GEMM);
    cudaFuncSetAttribute(glob_part_k, cudaFuncAttributeMaxDynamicSharedMemorySize, SMEM_GLOB);

    prep_k<<<BB, 256>>>(input_ids, attn_mask, idxg, klo);
    embed_ln_k<<<BS, 256>>>(input_ids, emb_tok, emb_pos, ln_e_s, ln_e_b, x, xhi, xlo);

    wsplit_all_k<<<TILES_ALL, dim3(32, 8)>>>(Wq, Wk, Wv, Wkg, Wvg, Wqg, Wo, Wf1, Wf2,
                                             bq, bk, bv, bkg, bvg, w, bcat);

    dim3 gTqkv(QS/128, BS/128 + 1);
    dim3 gT(DD/128, BS/128);
    dim3 gT1(FFN/128, BS/128);
    dim3 gBandM(SS/128, BH);
    dim3 gGlobP(NSEG, BH);

    for (int l = 0; l < LL; l++) {
        size_t base = (size_t)l * LWOFF;
        const float* bqg_l = bqg + l*DD;
        const float* bo_l  = bo  + l*DD;
        const float* bf1_l = bf1 + l*FFN; const float* bf2_l = bf2 + l*DD;

        tgemm_k<2><<<gTqkv, 256, SMEM_GEMM>>>(xhi, xlo, w+base+OFF_Q,
                                              bcat + l*QS, qkv, 0, 0, BS, QS, DD,
                                              w+base+OFF_QG, bqg_l, qg, idxg);

        band_mma_k<<<gBandM, 256>>>(bqh, bql, bkh, bvh, bvl, idxg, klo, xhi, xlo);

        glob_part_k<<<gGlobP, 256, SMEM_GLOB>>>(qg, qkv, attn_mask, pacc, pml);
        glob_comb_scat_k<<<BH, 256>>>(pacc, pml, idxg, xhi, xlo);

        tgemm_k<0><<<gT, 256, SMEM_GEMM>>>(xhi, xlo, w+base+OFF_O,
                                           bo_l, tmp, 0, 0, BS, DD, DD,
                                           0, 0, 0, 0);
        add_ln_k<<<BS, 256>>>(x, tmp, ln1_s + l*DD, ln1_b + l*DD, xhi, xlo);

        tgemm_k<1><<<gT1, 256, SMEM_GEMM>>>(xhi, xlo, w+base+OFF_F1,
                                            bf1_l, 0, ahi, alo, BS, FFN, DD,
                                            0, 0, 0, 0);
        tgemm_k<0><<<gT, 256, SMEM_GEMM>>>(ahi, alo, w+base+OFF_F2,
                                           bf2_l, tmp, 0, 0, BS, DD, FFN,
                                           0, 0, 0, 0);
        add_ln_k<<<BS, 256>>>(x, tmp, ln2_s + l*DD, ln2_b + l*DD, xhi, xlo);
    }

    int nrows = out_size / 7;
    classify_k<<<nrows, 256>>>(x, Wc, bc, lo_p, ro_p, out, nrows);
}